// round 14
// baseline (speedup 1.0000x reference)
#include <cuda_runtime.h>
#include <cuda_fp16.h>
#include <math.h>
#include <stdint.h>

#define BATCH 2
#define NPTS 4096
#define CH 256
#define NLAYER 4
#define FDIM 1024
#define CATDIM 1024
#define MROWS ((size_t)BATCH * NPTS)
#define LN_EPS 1e-6f
#define ATTN_EPS 1e-9f
#define LN_SPLIT 128
#define PSCALE 4096.0f
#define INV_PSCALE (1.0f / 4096.0f)

#define PART_BYTES 10240            // 128 rows * 80B (64B data + 16B pad)
#define STAGE4 (4 * PART_BYTES)     // 40960
#define STAGE3 (3 * PART_BYTES)     // 30720
#define MMA_SMEM4 (2 * STAGE4)      // 81920 (2-stage, 2 CTA/SM)
#define QK_SMEM   (3 * STAGE3)      // 92160 (3-stage, 2 CTA/SM)

// ---------------- scratch (device globals) ----------------------------------
__device__ float g_T[BATCH * NPTS * CH];
__device__ float g_X[BATCH * NPTS * CH];
__device__ float g_V[BATCH * NPTS * CH];
__device__ float g_O[BATCH * NPTS * CH];
__device__ __half g_P[(size_t)BATCH * NPTS * NPTS];   // 67MB: 4096*exp(S-tilemax)
__device__ float g_pmax[BATCH * 32 * NPTS];
__device__ float g_psum[BATCH * 32 * NPTS];
__device__ float g_f[BATCH * 32 * NPTS];
__device__ float g_colpart[8 * BATCH * NPTS];
__device__ float g_lnp0[LN_SPLIT * BATCH * CH];
__device__ float g_lnp1[LN_SPLIT * BATCH * CH];
__device__ float g_lncA[BATCH * CH];
__device__ float g_lncB[BATCH * CH];
__device__ unsigned g_lncnt;                 // zero-init, reset by last block
__device__ float g_bqkv[NLAYER * 768];

// half-split operand buffers
__device__ __half g_Xh[MROWS * CH],  g_Xl[MROWS * CH];
__device__ __half g_Qh[MROWS * CH];
__device__ __half g_Kh[MROWS * CH],  g_Kl[MROWS * CH];
__device__ __half g_Th[MROWS * CH],  g_Tl[MROWS * CH];
__device__ __half g_CATh[MROWS * CATDIM], g_CATl[MROWS * CATDIM];
__device__ __half g_Wqkvh[NLAYER * 768 * CH], g_Wqkvl[NLAYER * 768 * CH];
__device__ __half g_Woh[NLAYER * CH * CH], g_Wol[NLAYER * CH * CH];
__device__ __half g_W1h[CH * CH], g_W1l[CH * CH];
__device__ __half g_Wfh[CATDIM * FDIM], g_Wfl[CATDIM * FDIM];

// ---------------- PTX helpers ------------------------------------------------
__device__ __forceinline__ uint32_t smem_u32(const void* p) {
    uint32_t a;
    asm("{ .reg .u64 t; cvta.to.shared.u64 t, %1; cvt.u32.u64 %0, t; }"
        : "=r"(a) : "l"(p));
    return a;
}
__device__ __forceinline__ void cpa(uint32_t dst, const void* src) {
    asm volatile("cp.async.cg.shared.global [%0], [%1], 16;"
                 :: "r"(dst), "l"(src));
}
#define CP_COMMIT() asm volatile("cp.async.commit_group;" ::: "memory")
#define CP_WAIT1() asm volatile("cp.async.wait_group 1;" ::: "memory")
#define CP_WAIT0() asm volatile("cp.async.wait_group 0;" ::: "memory")

#define LDSM4(r, addr)                                                          \
    asm volatile("ldmatrix.sync.aligned.m8n8.x4.shared.b16 {%0,%1,%2,%3}, [%4];"\
        : "=r"((r)[0]), "=r"((r)[1]), "=r"((r)[2]), "=r"((r)[3]) : "r"(addr))

#define MMA16(d, a, b0r, b1r)                                                   \
    asm volatile("mma.sync.aligned.m16n8k16.row.col.f32.f16.f16.f32 "           \
        "{%0,%1,%2,%3}, {%4,%5,%6,%7}, {%8,%9}, {%0,%1,%2,%3};"                 \
        : "+f"((d)[0]), "+f"((d)[1]), "+f"((d)[2]), "+f"((d)[3])                \
        : "r"((a)[0]), "r"((a)[1]), "r"((a)[2]), "r"((a)[3]), "r"(b0r), "r"(b1r))

__device__ __forceinline__ void split2(float v0, float v1, __half2& hi, __half2& lo) {
    __half h0 = __float2half_rn(v0), h1 = __float2half_rn(v1);
    hi = __halves2half2(h0, h1);
    lo = __halves2half2(__float2half_rn(v0 - __half2float(h0)),
                        __float2half_rn(v1 - __half2float(h1)));
}

// ---------------- merged weight prep: transpose + fp16 hi/lo split ----------
// element space: [0,1048576) wq|wk|wv|wo (262144 each), [..,1114112) w1,
// [..,2162688) wf.  8448 blocks * 256 threads.
__global__ void k_prepW(const float* __restrict__ wq, const float* __restrict__ wk,
                        const float* __restrict__ wv, const float* __restrict__ wo,
                        const float* __restrict__ w1, const float* __restrict__ wf) {
    int e = blockIdx.x * 256 + threadIdx.x;
    float x;
    size_t o;
    __half *dh, *dl;
    if (e < 1048576) {
        int seg = e >> 18;
        int r = e & 262143;
        int lz = r >> 16;
        int ee = r & 65535;
        int k = ee >> 8, n = ee & 255;
        const float* W = (seg == 0) ? wq : (seg == 1) ? wk : (seg == 2) ? wv : wo;
        x = W[(size_t)lz * 65536 + ee];
        if (seg < 3) {
            o = (size_t)lz * 768 * CH + (size_t)seg * 256 * CH + (size_t)n * CH + k;
            dh = g_Wqkvh; dl = g_Wqkvl;
        } else {
            o = (size_t)lz * 65536 + (size_t)n * CH + k;
            dh = g_Woh; dl = g_Wol;
        }
    } else if (e < 1114112) {
        int ee = e - 1048576;
        int k = ee >> 8, n = ee & 255;
        x = w1[ee];
        o = (size_t)n * CH + k;
        dh = g_W1h; dl = g_W1l;
    } else {
        int ee = e - 1114112;
        int k = ee >> 10, n = ee & 1023;
        x = wf[ee];
        o = (size_t)n * CATDIM + k;
        dh = g_Wfh; dl = g_Wfl;
    }
    __half h = __float2half_rn(x);
    dh[o] = h;
    dl[o] = __float2half_rn(x - __half2float(h));
}

__global__ void k_prepB(const float* __restrict__ bq, const float* __restrict__ bk,
                        const float* __restrict__ bv) {
    int i = blockIdx.x * 256 + threadIdx.x;      // < NLAYER*768
    int lz = i / 768, r = i - lz * 768;
    float v = (r < 256) ? bq[lz * CH + r]
            : (r < 512) ? bk[lz * CH + r - 256]
                        : bv[lz * CH + r - 512];
    g_bqkv[i] = v;
}

// ---------------- input projection ------------------------------------------
__global__ void k_inproj(const float* __restrict__ in, const float* __restrict__ w0,
                         const float* __restrict__ b0) {
    int idx = blockIdx.x * 256 + threadIdx.x;
    int c = idx & (CH - 1);
    int bn = idx >> 8;
    const float* xp = in + bn * 3;
    float acc = b0[c];
    acc = fmaf(xp[0], w0[c], acc);
    acc = fmaf(xp[1], w0[CH + c], acc);
    acc = fmaf(xp[2], w0[2 * CH + c], acc);
    g_T[idx] = acc;
}

// ---------------- LayerNorm stats + fused coef (last block) -----------------
// grid (CH/64, BATCH, LN_SPLIT) = (4, 2, 128) = 1024 blocks
__global__ void k_ln_stats(const float* __restrict__ src,
                           const float* __restrict__ scale,
                           const float* __restrict__ bias) {
    int t = threadIdx.x;
    int ci = t & 63, nr = t >> 6;
    int c = blockIdx.x * 64 + ci;
    int b = blockIdx.y, sp = blockIdx.z;
    const float* p = src + ((size_t)b * NPTS + sp * (NPTS / LN_SPLIT)) * CH + c;
    float s0 = 0.f, s1 = 0.f;
    for (int n = nr; n < NPTS / LN_SPLIT; n += 4) {
        float v = p[(size_t)n * CH];
        s0 += v; s1 = fmaf(v, v, s1);
    }
    __shared__ float sh0[4][64], sh1[4][64];
    sh0[nr][ci] = s0; sh1[nr][ci] = s1;
    __syncthreads();
    if (nr == 0) {
        float a0 = 0.f, a1 = 0.f;
#pragma unroll
        for (int r = 0; r < 4; r++) { a0 += sh0[r][ci]; a1 += sh1[r][ci]; }
        g_lnp0[(sp * BATCH + b) * CH + c] = a0;
        g_lnp1[(sp * BATCH + b) * CH + c] = a1;
    }
    // last of 1024 blocks computes the coefficients
    __threadfence();
    __shared__ bool lastb;
    if (t == 0) lastb = (atomicAdd(&g_lncnt, 1u) == 1023u);
    __syncthreads();
    if (lastb) {
        for (int e = t; e < BATCH * CH; e += 256) {
            int cc = e & (CH - 1);
            float s0c = 0.f, s1c = 0.f;
#pragma unroll
            for (int j = 0; j < LN_SPLIT; j++) {
                s0c += g_lnp0[j * BATCH * CH + e];
                s1c += g_lnp1[j * BATCH * CH + e];
            }
            float mu = s0c * (1.0f / NPTS), m2 = s1c * (1.0f / NPTS);
            float rstd = rsqrtf(m2 - mu * mu + LN_EPS);
            float a = scale[cc] * rstd;
            g_lncA[e] = a;
            g_lncB[e] = bias[cc] - mu * a;
        }
        if (t == 0) g_lncnt = 0u;
    }
}

__global__ void k_ln_apply(const float* __restrict__ src, float* __restrict__ dstF,
                           __half* __restrict__ dH, __half* __restrict__ dL,
                           int ldH, int coff, const float* __restrict__ resid,
                           int relu_mode) {
    int i4 = blockIdx.x * 256 + threadIdx.x;
    int c4 = i4 & 63;
    int bn = i4 >> 6;
    int b = bn >> 12;
    float4 x = ((const float4*)src)[i4];
    float4 a = ((const float4*)g_lncA)[b * 64 + c4];
    float4 bb = ((const float4*)g_lncB)[b * 64 + c4];
    float4 y;
    y.x = fmaf(x.x, a.x, bb.x); y.y = fmaf(x.y, a.y, bb.y);
    y.z = fmaf(x.z, a.z, bb.z); y.w = fmaf(x.w, a.w, bb.w);
    if (relu_mode) {
        float4 r = ((const float4*)resid)[i4];
        y.x = fmaxf(y.x, 0.f) + r.x; y.y = fmaxf(y.y, 0.f) + r.y;
        y.z = fmaxf(y.z, 0.f) + r.z; y.w = fmaxf(y.w, 0.f) + r.w;
    }
    if (dstF) ((float4*)dstF)[i4] = y;
    __half2 h0, l0, h1, l1;
    split2(y.x, y.y, h0, l0);
    split2(y.z, y.w, h1, l1);
    size_t hidx = (size_t)bn * (ldH >> 2) + (coff >> 2) + c4;
    uint2 hv, lv;
    hv.x = *(uint32_t*)&h0; hv.y = *(uint32_t*)&h1;
    lv.x = *(uint32_t*)&l0; lv.y = *(uint32_t*)&l1;
    ((uint2*)dH)[hidx] = hv;
    ((uint2*)dL)[hidx] = lv;
}

// ---------------- fp16x3 tensor GEMM (2-stage, 2 CTA/SM): C = A * B^T -------
// MODE 0: Cf = acc + bias (fp32). MODE 3: fused QKV epilogue routing
// (bx 0-1 -> Q hi only; 2-3 -> K hi/lo split; 4-5 -> V fp32).
template <int MODE>
__global__ void __launch_bounds__(256, 2) k_mma(
    const __half* __restrict__ Ah, const __half* __restrict__ Al, int ldA,
    const __half* __restrict__ Bh, const __half* __restrict__ Bl, int ldB,
    const float* __restrict__ bias,
    float* __restrict__ Cf, __half* __restrict__ Chi, __half* __restrict__ Clo,
    int ldC, int K, __half* __restrict__ Chi2, __half* __restrict__ Clo2) {
    extern __shared__ char smraw[];
    uint32_t sb = smem_u32(smraw);
    int t = threadIdx.x, l = t & 31, wid = t >> 5;
    int wm = wid >> 2, wn = wid & 3;
    int m0 = blockIdx.y * 128, n0 = blockIdx.x * 128;
    const __half* gAh = Ah + (size_t)m0 * ldA;
    const __half* gAl = Al + (size_t)m0 * ldA;
    const __half* gBh = Bh + (size_t)n0 * ldB;
    const __half* gBl = Bl + (size_t)n0 * ldB;

    float acc[4][4][4];
#pragma unroll
    for (int i = 0; i < 4; i++)
#pragma unroll
        for (int j = 0; j < 4; j++)
#pragma unroll
            for (int r = 0; r < 4; r++) acc[i][j][r] = 0.f;

    int prow = t >> 1, pq0 = (t & 1) * 2;
#define PREFETCH4(cc) do {                                                      \
        uint32_t st_ = sb + (uint32_t)((cc) & 1) * STAGE4;                      \
        int ko_ = (cc) * 32;                                                    \
        _Pragma("unroll")                                                       \
        for (int i_ = 0; i_ < 2; i_++) {                                        \
            int q_ = pq0 + i_;                                                  \
            uint32_t d_ = st_ + prow * 80 + q_ * 16;                            \
            int go_ = ko_ + q_ * 8;                                             \
            cpa(d_,                gAh + (size_t)prow * ldA + go_);             \
            cpa(d_ + PART_BYTES,   gAl + (size_t)prow * ldA + go_);             \
            cpa(d_ + 2*PART_BYTES, gBh + (size_t)prow * ldB + go_);             \
            cpa(d_ + 3*PART_BYTES, gBl + (size_t)prow * ldB + go_);             \
        }                                                                       \
    } while (0)

    int NC = K >> 5;
    PREFETCH4(0);
    CP_COMMIT();
    for (int c = 0; c < NC; c++) {
        if (c + 1 < NC) {
            PREFETCH4(c + 1);
            CP_COMMIT();
            CP_WAIT1();
        } else {
            CP_WAIT0();
        }
        __syncthreads();
        uint32_t st = sb + (uint32_t)(c & 1) * STAGE4;
#pragma unroll
        for (int s16 = 0; s16 < 2; s16++) {
            uint32_t ah[4][4], al[4][4], bh[2][4], bl[2][4];
            uint32_t aoff = (uint32_t)((wm * 64 + (l & 15)) * 80 + s16 * 32 +
                                       (l >> 4) * 16);
#pragma unroll
            for (int mt = 0; mt < 4; mt++) {
                LDSM4(ah[mt], st + aoff + mt * 16 * 80);
                LDSM4(al[mt], st + PART_BYTES + aoff + mt * 16 * 80);
            }
            int g = l >> 3;
            uint32_t boff = (uint32_t)((wn * 32 + ((g >> 1) << 3) + (l & 7)) * 80 +
                                       s16 * 32 + (g & 1) * 16);
#pragma unroll
            for (int p = 0; p < 2; p++) {
                LDSM4(bh[p], st + 2 * PART_BYTES + boff + p * 16 * 80);
                LDSM4(bl[p], st + 3 * PART_BYTES + boff + p * 16 * 80);
            }
#pragma unroll
            for (int mt = 0; mt < 4; mt++)
#pragma unroll
                for (int nt = 0; nt < 4; nt++) {
                    int p = nt >> 1, h = (nt & 1) * 2;
                    MMA16(acc[mt][nt], ah[mt], bh[p][h], bh[p][h + 1]);
                    MMA16(acc[mt][nt], ah[mt], bl[p][h], bl[p][h + 1]);
                    MMA16(acc[mt][nt], al[mt], bh[p][h], bh[p][h + 1]);
                }
        }
        __syncthreads();
    }
#undef PREFETCH4

    if (MODE == 0) {
#pragma unroll
        for (int mt = 0; mt < 4; mt++)
#pragma unroll
            for (int hh = 0; hh < 2; hh++) {
                int row = m0 + wm * 64 + mt * 16 + (l >> 2) + hh * 8;
#pragma unroll
                for (int nt = 0; nt < 4; nt++) {
                    int n = n0 + wn * 32 + nt * 8 + 2 * (l & 3);
                    float v0 = acc[mt][nt][hh * 2] + bias[n];
                    float v1 = acc[mt][nt][hh * 2 + 1] + bias[n + 1];
                    *(float2*)(Cf + (size_t)row * ldC + n) = make_float2(v0, v1);
                }
            }
    } else {
        int bx = blockIdx.x;
        __half *dH = nullptr, *dL = nullptr;
        float* dF = nullptr;
        int nb;
        if (bx < 2)      { dH = Chi;  dL = nullptr; nb = 0;   }   // Q: hi only
        else if (bx < 4) { dH = Chi2; dL = Clo2;    nb = 256; }   // K: hi+lo
        else             { dF = Cf;                 nb = 512; }   // V: fp32
#pragma unroll
        for (int mt = 0; mt < 4; mt++)
#pragma unroll
            for (int hh = 0; hh < 2; hh++) {
                int row = m0 + wm * 64 + mt * 16 + (l >> 2) + hh * 8;
#pragma unroll
                for (int nt = 0; nt < 4; nt++) {
                    int n = n0 + wn * 32 + nt * 8 + 2 * (l & 3);
                    float v0 = acc[mt][nt][hh * 2] + bias[n];
                    float v1 = acc[mt][nt][hh * 2 + 1] + bias[n + 1];
                    int col = n - nb;
                    if (dF) {
                        *(float2*)(dF + (size_t)row * CH + col) = make_float2(v0, v1);
                    } else if (dL) {
                        __half2 hv, lv;
                        split2(v0, v1, hv, lv);
                        *(__half2*)(dH + (size_t)row * CH + col) = hv;
                        *(__half2*)(dL + (size_t)row * CH + col) = lv;
                    } else {
                        *(__half2*)(dH + (size_t)row * CH + col) =
                            __floats2half2_rn(v0, v1);
                    }
                }
            }
    }
}

// ---------------- QK kernel: 2-pass fp16, 3-stage, 2 CTA/SM -----------------
__global__ void __launch_bounds__(256, 2) k_qk(const __half* __restrict__ Ah,
                                               const __half* __restrict__ Bh,
                                               const __half* __restrict__ Bl) {
    extern __shared__ char smraw[];
    uint32_t sb = smem_u32(smraw);
    int t = threadIdx.x, l = t & 31, wid = t >> 5;
    int wm = wid >> 2, wn = wid & 3;
    int m0 = blockIdx.y * 128, n0 = blockIdx.x * 128;
    size_t z = (size_t)blockIdx.z * NPTS * CH;
    const __half* gAh = Ah + z + (size_t)m0 * CH;
    const __half* gBh = Bh + z + (size_t)n0 * CH;
    const __half* gBl = Bl + z + (size_t)n0 * CH;

    float acc[4][4][4];
#pragma unroll
    for (int i = 0; i < 4; i++)
#pragma unroll
        for (int j = 0; j < 4; j++)
#pragma unroll
            for (int r = 0; r < 4; r++) acc[i][j][r] = 0.f;

    int prow = t >> 1, pq0 = (t & 1) * 2;
#define PREFETCH3(cc) do {                                                      \
        uint32_t st_ = sb + (uint32_t)((cc) % 3) * STAGE3;                      \
        int ko_ = (cc) * 32;                                                    \
        _Pragma("unroll")                                                       \
        for (int i_ = 0; i_ < 2; i_++) {                                        \
            int q_ = pq0 + i_;                                                  \
            uint32_t d_ = st_ + prow * 80 + q_ * 16;                            \
            int go_ = ko_ + q_ * 8;                                             \
            cpa(d_,                gAh + (size_t)prow * CH + go_);              \
            cpa(d_ + PART_BYTES,   gBh + (size_t)prow * CH + go_);              \
            cpa(d_ + 2*PART_BYTES, gBl + (size_t)prow * CH + go_);              \
        }                                                                       \
    } while (0)

    PREFETCH3(0); CP_COMMIT();
    PREFETCH3(1); CP_COMMIT();
#pragma unroll
    for (int c = 0; c < 8; c++) {            // K=256 -> 8 chunks
        if (c < 7) { CP_WAIT1(); } else { CP_WAIT0(); }
        __syncthreads();
        if (c < 6) { PREFETCH3(c + 2); CP_COMMIT(); }
        uint32_t st = sb + (uint32_t)(c % 3) * STAGE3;
#pragma unroll
        for (int s16 = 0; s16 < 2; s16++) {
            uint32_t ah[4][4], bh[2][4], bl[2][4];
            uint32_t aoff = (uint32_t)((wm * 64 + (l & 15)) * 80 + s16 * 32 +
                                       (l >> 4) * 16);
#pragma unroll
            for (int mt = 0; mt < 4; mt++)
                LDSM4(ah[mt], st + aoff + mt * 16 * 80);
            int g = l >> 3;
            uint32_t boff = (uint32_t)((wn * 32 + ((g >> 1) << 3) + (l & 7)) * 80 +
                                       s16 * 32 + (g & 1) * 16);
#pragma unroll
            for (int p = 0; p < 2; p++) {
                LDSM4(bh[p], st + PART_BYTES + boff + p * 16 * 80);
                LDSM4(bl[p], st + 2 * PART_BYTES + boff + p * 16 * 80);
            }
#pragma unroll
            for (int mt = 0; mt < 4; mt++)
#pragma unroll
                for (int nt = 0; nt < 4; nt++) {
                    int p = nt >> 1, h = (nt & 1) * 2;
                    MMA16(acc[mt][nt], ah[mt], bh[p][h], bh[p][h + 1]);
                    MMA16(acc[mt][nt], ah[mt], bl[p][h], bl[p][h + 1]);
                }
        }
    }
#undef PREFETCH3

    // epilogue: tile rowmax -> P=4096*exp(S-max) fp16 -> global (staged)
    __half* pst = (__half*)smraw;                       // [128][136] halves
    float* wmaxs = (float*)(smraw + 36864);             // [128][4]
    float* wsums = wmaxs + 512;
    __syncthreads();
#pragma unroll
    for (int mt = 0; mt < 4; mt++)
#pragma unroll
        for (int hh = 0; hh < 2; hh++) {
            int row = wm * 64 + mt * 16 + hh * 8 + (l >> 2);
            float vmax = -3.0e38f;
#pragma unroll
            for (int nt = 0; nt < 4; nt++)
                vmax = fmaxf(vmax, fmaxf(acc[mt][nt][hh * 2],
                                         acc[mt][nt][hh * 2 + 1]));
#pragma unroll
            for (int off = 1; off <= 2; off <<= 1)
                vmax = fmaxf(vmax, __shfl_xor_sync(0xffffffffu, vmax, off));
            if ((l & 3) == 0) wmaxs[row * 4 + wn] = vmax;
        }
    __syncthreads();
#pragma unroll
    for (int mt = 0; mt < 4; mt++)
#pragma unroll
        for (int hh = 0; hh < 2; hh++) {
            int row = wm * 64 + mt * 16 + hh * 8 + (l >> 2);
            float M = fmaxf(fmaxf(wmaxs[row * 4], wmaxs[row * 4 + 1]),
                            fmaxf(wmaxs[row * 4 + 2], wmaxs[row * 4 + 3]));
            float s = 0.f;
#pragma unroll
            for (int nt = 0; nt < 4; nt++) {
                float e0 = __expf(acc[mt][nt][hh * 2] - M) * PSCALE;
                float e1 = __expf(acc[mt][nt][hh * 2 + 1] - M) * PSCALE;
                s += e0 + e1;
                *(__half2*)&pst[row * 136 + wn * 32 + nt * 8 + 2 * (l & 3)] =
                    __floats2half2_rn(e0, e1);
            }
#pragma unroll
            for (int off = 1; off <= 2; off <<= 1)
                s += __shfl_xor_sync(0xffffffffu, s, off);
            if ((l & 3) == 0) wsums[row * 4 + wn] = s;
        }
    __syncthreads();
    int zb = blockIdx.z;
    if (t < 128) {
        float M = fmaxf(fmaxf(wmaxs[t * 4], wmaxs[t * 4 + 1]),
                        fmaxf(wmaxs[t * 4 + 2], wmaxs[t * 4 + 3]));
        float S = (wsums[t * 4] + wsums[t * 4 + 1] + wsums[t * 4 + 2] +
                   wsums[t * 4 + 3]) * INV_PSCALE;
        g_pmax[(zb * 32 + blockIdx.x) * NPTS + m0 + t] = M;
        g_psum[(zb * 32 + blockIdx.x) * NPTS + m0 + t] = S;
    }
    __half* Pb = g_P + (size_t)zb * NPTS * NPTS;
#pragma unroll
    for (int i = 0; i < 8; i++) {
        int f = t + i * 256;
        int r = f >> 4, c8 = f & 15;
        *(uint4*)(Pb + (size_t)(m0 + r) * NPTS + n0 + c8 * 8) =
            *(const uint4*)&pst[r * 136 + c8 * 8];
    }
}

// ---------------- combine row partials, emit correction factors ------------
__global__ void k_rowstats() {
    int i = blockIdx.x * 256 + threadIdx.x;   // < B*N
    int b = i >> 12, m = i & (NPTS - 1);
    float pm[32];
    float mx = -3.0e38f;
#pragma unroll
    for (int j = 0; j < 32; j++) {
        pm[j] = g_pmax[(b * 32 + j) * NPTS + m];
        mx = fmaxf(mx, pm[j]);
    }
    float s = 0.f;
#pragma unroll
    for (int j = 0; j < 32; j++)
        s += g_psum[(b * 32 + j) * NPTS + m] * __expf(pm[j] - mx);
    float inv = INV_PSCALE / s;
#pragma unroll
    for (int j = 0; j < 32; j++)
        g_f[(b * 32 + j) * NPTS + m] = __expf(pm[j] - mx) * inv;
}

// ---------------- pass 2: column sums = fp16 half2 GEMV ---------------------
__global__ void k_colsum() {      // grid (8, 8, BATCH), 256 threads
    __shared__ float fs[4][512];
    int ng = blockIdx.x, mc = blockIdx.y, b = blockIdx.z, t = threadIdx.x;
#pragma unroll
    for (int jj = 0; jj < 4; jj++)
        for (int i = t; i < 512; i += 256)
            fs[jj][i] = g_f[(b * 32 + ng * 4 + jj) * NPTS + mc * 512 + i];
    __syncthreads();
    int n = ng * 512 + 2 * t;
    int jj = t >> 6;
    const __half* P = g_P + (size_t)b * NPTS * NPTS + (size_t)(mc * 512) * NPTS + n;
    float2 a0 = {0, 0}, a1 = {0, 0}, a2 = {0, 0}, a3 = {0, 0};
#pragma unroll 8
    for (int m = 0; m < 512; m += 4) {
        float2 p0 = __half22float2(*(const __half2*)(P + (size_t)(m + 0) * NPTS));
        float2 p1 = __half22float2(*(const __half2*)(P + (size_t)(m + 1) * NPTS));
        float2 p2 = __half22float2(*(const __half2*)(P + (size_t)(m + 2) * NPTS));
        float2 p3 = __half22float2(*(const __half2*)(P + (size_t)(m + 3) * NPTS));
        a0.x = fmaf(p0.x, fs[jj][m + 0], a0.x); a0.y = fmaf(p0.y, fs[jj][m + 0], a0.y);
        a1.x = fmaf(p1.x, fs[jj][m + 1], a1.x); a1.y = fmaf(p1.y, fs[jj][m + 1], a1.y);
        a2.x = fmaf(p2.x, fs[jj][m + 2], a2.x); a2.y = fmaf(p2.y, fs[jj][m + 2], a2.y);
        a3.x = fmaf(p3.x, fs[jj][m + 3], a3.x); a3.y = fmaf(p3.y, fs[jj][m + 3], a3.y);
    }
    float2 r;
    r.x = (a0.x + a1.x) + (a2.x + a3.x);
    r.y = (a0.y + a1.y) + (a2.y + a3.y);
    *(float2*)(&g_colpart[(mc * BATCH + b) * NPTS + n]) = r;
}

// ---------------- gate + gate*V + split -------------------------------------
__global__ void k_gatev() {
    int i4 = blockIdx.x * 256 + threadIdx.x;
    int bn = i4 >> 6;
    float c = 0.f;
#pragma unroll
    for (int y = 0; y < 8; y++) c += g_colpart[y * BATCH * NPTS + bn];
    float gt = c / (ATTN_EPS + c);
    float4 v = ((const float4*)g_V)[i4];
    __half2 h0, l0, h1, l1;
    split2(gt * v.x, gt * v.y, h0, l0);
    split2(gt * v.z, gt * v.w, h1, l1);
    uint2 hv, lv;
    hv.x = *(uint32_t*)&h0; hv.y = *(uint32_t*)&h1;
    lv.x = *(uint32_t*)&l0; lv.y = *(uint32_t*)&l1;
    ((uint2*)g_Th)[i4] = hv;
    ((uint2*)g_Tl)[i4] = lv;
}

// ---------------------------------------------------------------------------
extern "C" void kernel_launch(void* const* d_in, const int* in_sizes, int n_in,
                              void* d_out, int out_size) {
    const float* inp  = (const float*)d_in[0];
    const float* w0   = (const float*)d_in[1];
    const float* b0   = (const float*)d_in[2];
    const float* ln0s = (const float*)d_in[3];
    const float* ln0b = (const float*)d_in[4];
    const float* w1   = (const float*)d_in[5];
    const float* b1   = (const float*)d_in[6];
    const float* ln1s = (const float*)d_in[7];
    const float* ln1b = (const float*)d_in[8];
    const float* wq   = (const float*)d_in[9];
    const float* bq   = (const float*)d_in[10];
    const float* wk   = (const float*)d_in[11];
    const float* bk   = (const float*)d_in[12];
    const float* wv   = (const float*)d_in[13];
    const float* bv   = (const float*)d_in[14];
    const float* wo   = (const float*)d_in[15];
    const float* bo   = (const float*)d_in[16];
    const float* alns = (const float*)d_in[17];
    const float* alnb = (const float*)d_in[18];
    const float* wf   = (const float*)d_in[19];
    const float* bf   = (const float*)d_in[20];

    float *T, *X, *V, *O, *BQKV;
    __half *Xh, *Xl, *Qh, *Kh, *Kl, *Th, *Tl, *CATh, *CATl;
    __half *Wqkvh, *Wqkvl, *Woh, *Wol, *W1h, *W1l, *Wfh, *Wfl;
    cudaGetSymbolAddress((void**)&T, g_T);
    cudaGetSymbolAddress((void**)&X, g_X);
    cudaGetSymbolAddress((void**)&V, g_V);
    cudaGetSymbolAddress((void**)&O, g_O);
    cudaGetSymbolAddress((void**)&BQKV, g_bqkv);
    cudaGetSymbolAddress((void**)&Xh, g_Xh);   cudaGetSymbolAddress((void**)&Xl, g_Xl);
    cudaGetSymbolAddress((void**)&Qh, g_Qh);
    cudaGetSymbolAddress((void**)&Kh, g_Kh);   cudaGetSymbolAddress((void**)&Kl, g_Kl);
    cudaGetSymbolAddress((void**)&Th, g_Th);   cudaGetSymbolAddress((void**)&Tl, g_Tl);
    cudaGetSymbolAddress((void**)&CATh, g_CATh); cudaGetSymbolAddress((void**)&CATl, g_CATl);
    cudaGetSymbolAddress((void**)&Wqkvh, g_Wqkvh); cudaGetSymbolAddress((void**)&Wqkvl, g_Wqkvl);
    cudaGetSymbolAddress((void**)&Woh, g_Woh); cudaGetSymbolAddress((void**)&Wol, g_Wol);
    cudaGetSymbolAddress((void**)&W1h, g_W1h); cudaGetSymbolAddress((void**)&W1l, g_W1l);
    cudaGetSymbolAddress((void**)&Wfh, g_Wfh); cudaGetSymbolAddress((void**)&Wfl, g_Wfl);

    cudaFuncSetAttribute(k_mma<0>, cudaFuncAttributeMaxDynamicSharedMemorySize, MMA_SMEM4);
    cudaFuncSetAttribute(k_mma<3>, cudaFuncAttributeMaxDynamicSharedMemorySize, MMA_SMEM4);
    cudaFuncSetAttribute(k_qk, cudaFuncAttributeMaxDynamicSharedMemorySize, QK_SMEM);

    dim3 lnStats(CH / 64, BATCH, LN_SPLIT);          // (4, 2, 128) = 1024 blocks
    const int applyGrid = (int)(MROWS * CH / 4 / 256);
    dim3 gridC(CH / 128, (int)(MROWS / 128));        // (2, 64)
    dim3 gridQKV(768 / 128, (int)(MROWS / 128));     // (6, 64)
    dim3 gridQK(NPTS / 128, NPTS / 128, BATCH);      // (32, 32, 2)
    dim3 gridF(FDIM / 128, (int)(MROWS / 128));      // (8, 64)

    // prep: one merged weight transpose/split + bias pack
    k_prepW<<<8448, 256>>>(wq, wk, wv, wo, w1, wf);
    k_prepB<<<NLAYER * 768 / 256, 256>>>(bq, bk, bv);

    // pre-conv stack
    k_inproj<<<BATCH * NPTS * CH / 256, 256>>>(inp, w0, b0);
    k_ln_stats<<<lnStats, 256>>>(T, ln0s, ln0b);
    k_ln_apply<<<applyGrid, 256>>>(T, nullptr, Xh, Xl, CH, 0, nullptr, 0);
    k_mma<0><<<gridC, 256, MMA_SMEM4>>>(Xh, Xl, CH, W1h, W1l, CH, b1,
                                        O, nullptr, nullptr, CH, CH,
                                        nullptr, nullptr);
    k_ln_stats<<<lnStats, 256>>>(O, ln1s, ln1b);
    k_ln_apply<<<applyGrid, 256>>>(O, X, Xh, Xl, CH, 0, nullptr, 0);

    for (int i = 0; i < NLAYER; i++) {
        const __half* Ahh = (i == 0) ? Xh : CATh + (size_t)(i - 1) * CH;
        const __half* All = (i == 0) ? Xl : CATl + (size_t)(i - 1) * CH;
        int ldA = (i == 0) ? CH : CATDIM;
        // fused QKV
        k_mma<3><<<gridQKV, 256, MMA_SMEM4>>>(
            Ahh, All, ldA, Wqkvh + (size_t)i * 768 * CH,
            Wqkvl + (size_t)i * 768 * CH, CH, BQKV + i * 768,
            V, Qh, nullptr, CH, CH, Kh, Kl);
        k_qk<<<gridQK, 256, QK_SMEM>>>(Qh, Kh, Kl);
        k_rowstats<<<BATCH * NPTS / 256, 256>>>();
        k_colsum<<<dim3(8, 8, BATCH), 256>>>();
        k_gatev<<<(int)(MROWS * CH / 4 / 256), 256>>>();
        k_mma<0><<<gridC, 256, MMA_SMEM4>>>(Th, Tl, CH,
                                            Woh + (size_t)i * CH * CH,
                                            Wol + (size_t)i * CH * CH,
                                            CH, bo + i * CH, O, nullptr, nullptr,
                                            CH, CH, nullptr, nullptr);
        k_ln_stats<<<lnStats, 256>>>(O, alns + i * CH, alnb + i * CH);
        k_ln_apply<<<applyGrid, 256>>>(O, X, CATh, CATl, CATDIM, i * CH, X, 1);
    }

    k_mma<0><<<gridF, 256, MMA_SMEM4>>>(CATh, CATl, CATDIM, Wfh, Wfl, CATDIM, bf,
                                        (float*)d_out, nullptr, nullptr, FDIM,
                                        CATDIM, nullptr, nullptr);
}

// round 15
// speedup vs baseline: 1.0651x; 1.0651x over previous
#include <cuda_runtime.h>
#include <cuda_fp16.h>
#include <math.h>
#include <stdint.h>

#define BATCH 2
#define NPTS 4096
#define CH 256
#define NLAYER 4
#define FDIM 1024
#define CATDIM 1024
#define MROWS ((size_t)BATCH * NPTS)
#define LN_EPS 1e-6f
#define ATTN_EPS 1e-9f
#define LN_SPLIT 32
#define PSCALE 4096.0f
#define INV_PSCALE (1.0f / 4096.0f)

#define PART_BYTES 10240            // 128 rows * 80B (64B data + 16B pad)
#define STAGE4 (4 * PART_BYTES)     // 40960
#define STAGE3 (3 * PART_BYTES)     // 30720
#define MMA_SMEM4 (2 * STAGE4)      // 81920 (2-stage, 2 CTA/SM)
#define QK_SMEM   (3 * STAGE3)      // 92160 (3-stage, 2 CTA/SM)

// ---------------- scratch (device globals) ----------------------------------
__device__ float g_T[BATCH * NPTS * CH];
__device__ float g_X[BATCH * NPTS * CH];
__device__ float g_V[BATCH * NPTS * CH];
__device__ float g_O[BATCH * NPTS * CH];
__device__ __half g_P[(size_t)BATCH * NPTS * NPTS];   // 67MB: 4096*exp(S-tilemax)
__device__ float g_pmax[BATCH * 32 * NPTS];
__device__ float g_psum[BATCH * 32 * NPTS];
__device__ float g_f[BATCH * 32 * NPTS];
__device__ float g_colpart[16 * BATCH * NPTS];
__device__ float g_lnp0[LN_SPLIT * BATCH * CH];
__device__ float g_lnp1[LN_SPLIT * BATCH * CH];
__device__ float g_lncA[BATCH * CH];
__device__ float g_lncB[BATCH * CH];
__device__ unsigned g_lncnt;                 // zero-init, reset by last block
__device__ float g_bqkv[NLAYER * 768];

// half-split operand buffers
__device__ __half g_Xh[MROWS * CH],  g_Xl[MROWS * CH];
__device__ __half g_Qh[MROWS * CH];
__device__ __half g_Kh[MROWS * CH],  g_Kl[MROWS * CH];
__device__ __half g_Th[MROWS * CH],  g_Tl[MROWS * CH];
__device__ __half g_CATh[MROWS * CATDIM], g_CATl[MROWS * CATDIM];
__device__ __half g_Wqkvh[NLAYER * 768 * CH], g_Wqkvl[NLAYER * 768 * CH];
__device__ __half g_Woh[NLAYER * CH * CH], g_Wol[NLAYER * CH * CH];
__device__ __half g_W1h[CH * CH], g_W1l[CH * CH];
__device__ __half g_Wfh[CATDIM * FDIM], g_Wfl[CATDIM * FDIM];

// ---------------- PTX helpers ------------------------------------------------
__device__ __forceinline__ uint32_t smem_u32(const void* p) {
    uint32_t a;
    asm("{ .reg .u64 t; cvta.to.shared.u64 t, %1; cvt.u32.u64 %0, t; }"
        : "=r"(a) : "l"(p));
    return a;
}
__device__ __forceinline__ void cpa(uint32_t dst, const void* src) {
    asm volatile("cp.async.cg.shared.global [%0], [%1], 16;"
                 :: "r"(dst), "l"(src));
}
#define CP_COMMIT() asm volatile("cp.async.commit_group;" ::: "memory")
#define CP_WAIT1() asm volatile("cp.async.wait_group 1;" ::: "memory")
#define CP_WAIT0() asm volatile("cp.async.wait_group 0;" ::: "memory")

#define LDSM4(r, addr)                                                          \
    asm volatile("ldmatrix.sync.aligned.m8n8.x4.shared.b16 {%0,%1,%2,%3}, [%4];"\
        : "=r"((r)[0]), "=r"((r)[1]), "=r"((r)[2]), "=r"((r)[3]) : "r"(addr))

#define MMA16(d, a, b0r, b1r)                                                   \
    asm volatile("mma.sync.aligned.m16n8k16.row.col.f32.f16.f16.f32 "           \
        "{%0,%1,%2,%3}, {%4,%5,%6,%7}, {%8,%9}, {%0,%1,%2,%3};"                 \
        : "+f"((d)[0]), "+f"((d)[1]), "+f"((d)[2]), "+f"((d)[3])                \
        : "r"((a)[0]), "r"((a)[1]), "r"((a)[2]), "r"((a)[3]), "r"(b0r), "r"(b1r))

__device__ __forceinline__ void split2(float v0, float v1, __half2& hi, __half2& lo) {
    __half h0 = __float2half_rn(v0), h1 = __float2half_rn(v1);
    hi = __halves2half2(h0, h1);
    lo = __halves2half2(__float2half_rn(v0 - __half2float(h0)),
                        __float2half_rn(v1 - __half2float(h1)));
}

// ---------------- merged weight prep: transpose + fp16 hi/lo split ----------
__global__ void k_prepW(const float* __restrict__ wq, const float* __restrict__ wk,
                        const float* __restrict__ wv, const float* __restrict__ wo,
                        const float* __restrict__ w1, const float* __restrict__ wf) {
    int e = blockIdx.x * 256 + threadIdx.x;
    float x;
    size_t o;
    __half *dh, *dl;
    if (e < 1048576) {
        int seg = e >> 18;
        int r = e & 262143;
        int lz = r >> 16;
        int ee = r & 65535;
        int k = ee >> 8, n = ee & 255;
        const float* W = (seg == 0) ? wq : (seg == 1) ? wk : (seg == 2) ? wv : wo;
        x = W[(size_t)lz * 65536 + ee];
        if (seg < 3) {
            o = (size_t)lz * 768 * CH + (size_t)seg * 256 * CH + (size_t)n * CH + k;
            dh = g_Wqkvh; dl = g_Wqkvl;
        } else {
            o = (size_t)lz * 65536 + (size_t)n * CH + k;
            dh = g_Woh; dl = g_Wol;
        }
    } else if (e < 1114112) {
        int ee = e - 1048576;
        int k = ee >> 8, n = ee & 255;
        x = w1[ee];
        o = (size_t)n * CH + k;
        dh = g_W1h; dl = g_W1l;
    } else {
        int ee = e - 1114112;
        int k = ee >> 10, n = ee & 1023;
        x = wf[ee];
        o = (size_t)n * CATDIM + k;
        dh = g_Wfh; dl = g_Wfl;
    }
    __half h = __float2half_rn(x);
    dh[o] = h;
    dl[o] = __float2half_rn(x - __half2float(h));
}

__global__ void k_prepB(const float* __restrict__ bq, const float* __restrict__ bk,
                        const float* __restrict__ bv) {
    int i = blockIdx.x * 256 + threadIdx.x;      // < NLAYER*768
    int lz = i / 768, r = i - lz * 768;
    float v = (r < 256) ? bq[lz * CH + r]
            : (r < 512) ? bk[lz * CH + r - 256]
                        : bv[lz * CH + r - 512];
    g_bqkv[i] = v;
}

// ---------------- input projection ------------------------------------------
__global__ void k_inproj(const float* __restrict__ in, const float* __restrict__ w0,
                         const float* __restrict__ b0) {
    int idx = blockIdx.x * 256 + threadIdx.x;
    int c = idx & (CH - 1);
    int bn = idx >> 8;
    const float* xp = in + bn * 3;
    float acc = b0[c];
    acc = fmaf(xp[0], w0[c], acc);
    acc = fmaf(xp[1], w0[CH + c], acc);
    acc = fmaf(xp[2], w0[2 * CH + c], acc);
    g_T[idx] = acc;
}

// ---------------- LayerNorm stats (float4) + fused coef (last block) --------
// grid (CH/64, BATCH, LN_SPLIT) = (4, 2, 32) = 256 blocks
__global__ void k_ln_stats(const float* __restrict__ src,
                           const float* __restrict__ scale,
                           const float* __restrict__ bias) {
    int t = threadIdx.x;
    int c4i = t & 15, nr = t >> 4;        // 16 float4 columns x 16 row groups
    int c0 = blockIdx.x * 64 + c4i * 4;
    int b = blockIdx.y, sp = blockIdx.z;
    const float4* p = (const float4*)(src +
        ((size_t)b * NPTS + sp * (NPTS / LN_SPLIT)) * CH + c0);
    float4 s0 = {0, 0, 0, 0}, s1 = {0, 0, 0, 0};
#pragma unroll
    for (int n = nr; n < NPTS / LN_SPLIT; n += 16) {
        float4 v = p[(size_t)n * (CH / 4)];
        s0.x += v.x; s1.x = fmaf(v.x, v.x, s1.x);
        s0.y += v.y; s1.y = fmaf(v.y, v.y, s1.y);
        s0.z += v.z; s1.z = fmaf(v.z, v.z, s1.z);
        s0.w += v.w; s1.w = fmaf(v.w, v.w, s1.w);
    }
    __shared__ float sh0[16][68], sh1[16][68];
    sh0[nr][c4i * 4 + 0] = s0.x; sh1[nr][c4i * 4 + 0] = s1.x;
    sh0[nr][c4i * 4 + 1] = s0.y; sh1[nr][c4i * 4 + 1] = s1.y;
    sh0[nr][c4i * 4 + 2] = s0.z; sh1[nr][c4i * 4 + 2] = s1.z;
    sh0[nr][c4i * 4 + 3] = s0.w; sh1[nr][c4i * 4 + 3] = s1.w;
    __syncthreads();
    if (t < 64) {
        float a0 = 0.f, a1 = 0.f;
#pragma unroll
        for (int r = 0; r < 16; r++) { a0 += sh0[r][t]; a1 += sh1[r][t]; }
        g_lnp0[(sp * BATCH + b) * CH + blockIdx.x * 64 + t] = a0;
        g_lnp1[(sp * BATCH + b) * CH + blockIdx.x * 64 + t] = a1;
    }
    // last of 256 blocks computes the coefficients
    __threadfence();
    __shared__ bool lastb;
    if (t == 0) lastb = (atomicAdd(&g_lncnt, 1u) == 255u);
    __syncthreads();
    if (lastb) {
        for (int e = t; e < BATCH * CH; e += 256) {
            int cc = e & (CH - 1);
            float s0c = 0.f, s1c = 0.f;
#pragma unroll
            for (int j = 0; j < LN_SPLIT; j++) {
                s0c += g_lnp0[j * BATCH * CH + e];
                s1c += g_lnp1[j * BATCH * CH + e];
            }
            float mu = s0c * (1.0f / NPTS), m2 = s1c * (1.0f / NPTS);
            float rstd = rsqrtf(m2 - mu * mu + LN_EPS);
            float a = scale[cc] * rstd;
            g_lncA[e] = a;
            g_lncB[e] = bias[cc] - mu * a;
        }
        if (t == 0) g_lncnt = 0u;
    }
}

__global__ void k_ln_apply(const float* __restrict__ src, float* __restrict__ dstF,
                           __half* __restrict__ dH, __half* __restrict__ dL,
                           int ldH, int coff, const float* __restrict__ resid,
                           int relu_mode) {
    int i4 = blockIdx.x * 256 + threadIdx.x;
    int c4 = i4 & 63;
    int bn = i4 >> 6;
    int b = bn >> 12;
    float4 x = ((const float4*)src)[i4];
    float4 a = ((const float4*)g_lncA)[b * 64 + c4];
    float4 bb = ((const float4*)g_lncB)[b * 64 + c4];
    float4 y;
    y.x = fmaf(x.x, a.x, bb.x); y.y = fmaf(x.y, a.y, bb.y);
    y.z = fmaf(x.z, a.z, bb.z); y.w = fmaf(x.w, a.w, bb.w);
    if (relu_mode) {
        float4 r = ((const float4*)resid)[i4];
        y.x = fmaxf(y.x, 0.f) + r.x; y.y = fmaxf(y.y, 0.f) + r.y;
        y.z = fmaxf(y.z, 0.f) + r.z; y.w = fmaxf(y.w, 0.f) + r.w;
    }
    if (dstF) ((float4*)dstF)[i4] = y;
    __half2 h0, l0, h1, l1;
    split2(y.x, y.y, h0, l0);
    split2(y.z, y.w, h1, l1);
    size_t hidx = (size_t)bn * (ldH >> 2) + (coff >> 2) + c4;
    uint2 hv, lv;
    hv.x = *(uint32_t*)&h0; hv.y = *(uint32_t*)&h1;
    lv.x = *(uint32_t*)&l0; lv.y = *(uint32_t*)&l1;
    ((uint2*)dH)[hidx] = hv;
    ((uint2*)dL)[hidx] = lv;
}

// ---------------- fp16x3 tensor GEMM (2-stage, 2 CTA/SM): C = A * B^T -------
// MODE 0: Cf = acc + bias (fp32). MODE 3: fused QKV epilogue routing
// (bx 0-1 -> Q hi only; 2-3 -> K hi/lo split; 4-5 -> V fp32).
template <int MODE>
__global__ void __launch_bounds__(256, 2) k_mma(
    const __half* __restrict__ Ah, const __half* __restrict__ Al, int ldA,
    const __half* __restrict__ Bh, const __half* __restrict__ Bl, int ldB,
    const float* __restrict__ bias,
    float* __restrict__ Cf, __half* __restrict__ Chi, __half* __restrict__ Clo,
    int ldC, int K, __half* __restrict__ Chi2, __half* __restrict__ Clo2) {
    extern __shared__ char smraw[];
    uint32_t sb = smem_u32(smraw);
    int t = threadIdx.x, l = t & 31, wid = t >> 5;
    int wm = wid >> 2, wn = wid & 3;
    int m0 = blockIdx.y * 128, n0 = blockIdx.x * 128;
    const __half* gAh = Ah + (size_t)m0 * ldA;
    const __half* gAl = Al + (size_t)m0 * ldA;
    const __half* gBh = Bh + (size_t)n0 * ldB;
    const __half* gBl = Bl + (size_t)n0 * ldB;

    float acc[4][4][4];
#pragma unroll
    for (int i = 0; i < 4; i++)
#pragma unroll
        for (int j = 0; j < 4; j++)
#pragma unroll
            for (int r = 0; r < 4; r++) acc[i][j][r] = 0.f;

    int prow = t >> 1, pq0 = (t & 1) * 2;
#define PREFETCH4(cc) do {                                                      \
        uint32_t st_ = sb + (uint32_t)((cc) & 1) * STAGE4;                      \
        int ko_ = (cc) * 32;                                                    \
        _Pragma("unroll")                                                       \
        for (int i_ = 0; i_ < 2; i_++) {                                        \
            int q_ = pq0 + i_;                                                  \
            uint32_t d_ = st_ + prow * 80 + q_ * 16;                            \
            int go_ = ko_ + q_ * 8;                                             \
            cpa(d_,                gAh + (size_t)prow * ldA + go_);             \
            cpa(d_ + PART_BYTES,   gAl + (size_t)prow * ldA + go_);             \
            cpa(d_ + 2*PART_BYTES, gBh + (size_t)prow * ldB + go_);             \
            cpa(d_ + 3*PART_BYTES, gBl + (size_t)prow * ldB + go_);             \
        }                                                                       \
    } while (0)

    int NC = K >> 5;
    PREFETCH4(0);
    CP_COMMIT();
    for (int c = 0; c < NC; c++) {
        if (c + 1 < NC) {
            PREFETCH4(c + 1);
            CP_COMMIT();
            CP_WAIT1();
        } else {
            CP_WAIT0();
        }
        __syncthreads();
        uint32_t st = sb + (uint32_t)(c & 1) * STAGE4;
#pragma unroll
        for (int s16 = 0; s16 < 2; s16++) {
            uint32_t ah[4][4], al[4][4], bh[2][4], bl[2][4];
            uint32_t aoff = (uint32_t)((wm * 64 + (l & 15)) * 80 + s16 * 32 +
                                       (l >> 4) * 16);
#pragma unroll
            for (int mt = 0; mt < 4; mt++) {
                LDSM4(ah[mt], st + aoff + mt * 16 * 80);
                LDSM4(al[mt], st + PART_BYTES + aoff + mt * 16 * 80);
            }
            int g = l >> 3;
            uint32_t boff = (uint32_t)((wn * 32 + ((g >> 1) << 3) + (l & 7)) * 80 +
                                       s16 * 32 + (g & 1) * 16);
#pragma unroll
            for (int p = 0; p < 2; p++) {
                LDSM4(bh[p], st + 2 * PART_BYTES + boff + p * 16 * 80);
                LDSM4(bl[p], st + 3 * PART_BYTES + boff + p * 16 * 80);
            }
#pragma unroll
            for (int mt = 0; mt < 4; mt++)
#pragma unroll
                for (int nt = 0; nt < 4; nt++) {
                    int p = nt >> 1, h = (nt & 1) * 2;
                    MMA16(acc[mt][nt], ah[mt], bh[p][h], bh[p][h + 1]);
                    MMA16(acc[mt][nt], ah[mt], bl[p][h], bl[p][h + 1]);
                    MMA16(acc[mt][nt], al[mt], bh[p][h], bh[p][h + 1]);
                }
        }
        __syncthreads();
    }
#undef PREFETCH4

    if (MODE == 0) {
#pragma unroll
        for (int mt = 0; mt < 4; mt++)
#pragma unroll
            for (int hh = 0; hh < 2; hh++) {
                int row = m0 + wm * 64 + mt * 16 + (l >> 2) + hh * 8;
#pragma unroll
                for (int nt = 0; nt < 4; nt++) {
                    int n = n0 + wn * 32 + nt * 8 + 2 * (l & 3);
                    float v0 = acc[mt][nt][hh * 2] + bias[n];
                    float v1 = acc[mt][nt][hh * 2 + 1] + bias[n + 1];
                    *(float2*)(Cf + (size_t)row * ldC + n) = make_float2(v0, v1);
                }
            }
    } else {
        int bx = blockIdx.x;
        __half *dH = nullptr, *dL = nullptr;
        float* dF = nullptr;
        int nb;
        if (bx < 2)      { dH = Chi;  dL = nullptr; nb = 0;   }   // Q: hi only
        else if (bx < 4) { dH = Chi2; dL = Clo2;    nb = 256; }   // K: hi+lo
        else             { dF = Cf;                 nb = 512; }   // V: fp32
#pragma unroll
        for (int mt = 0; mt < 4; mt++)
#pragma unroll
            for (int hh = 0; hh < 2; hh++) {
                int row = m0 + wm * 64 + mt * 16 + (l >> 2) + hh * 8;
#pragma unroll
                for (int nt = 0; nt < 4; nt++) {
                    int n = n0 + wn * 32 + nt * 8 + 2 * (l & 3);
                    float v0 = acc[mt][nt][hh * 2] + bias[n];
                    float v1 = acc[mt][nt][hh * 2 + 1] + bias[n + 1];
                    int col = n - nb;
                    if (dF) {
                        *(float2*)(dF + (size_t)row * CH + col) = make_float2(v0, v1);
                    } else if (dL) {
                        __half2 hv, lv;
                        split2(v0, v1, hv, lv);
                        *(__half2*)(dH + (size_t)row * CH + col) = hv;
                        *(__half2*)(dL + (size_t)row * CH + col) = lv;
                    } else {
                        *(__half2*)(dH + (size_t)row * CH + col) =
                            __floats2half2_rn(v0, v1);
                    }
                }
            }
    }
}

// ---------------- QK kernel: 2-pass fp16, 3-stage, 2 CTA/SM -----------------
__global__ void __launch_bounds__(256, 2) k_qk(const __half* __restrict__ Ah,
                                               const __half* __restrict__ Bh,
                                               const __half* __restrict__ Bl) {
    extern __shared__ char smraw[];
    uint32_t sb = smem_u32(smraw);
    int t = threadIdx.x, l = t & 31, wid = t >> 5;
    int wm = wid >> 2, wn = wid & 3;
    int m0 = blockIdx.y * 128, n0 = blockIdx.x * 128;
    size_t z = (size_t)blockIdx.z * NPTS * CH;
    const __half* gAh = Ah + z + (size_t)m0 * CH;
    const __half* gBh = Bh + z + (size_t)n0 * CH;
    const __half* gBl = Bl + z + (size_t)n0 * CH;

    float acc[4][4][4];
#pragma unroll
    for (int i = 0; i < 4; i++)
#pragma unroll
        for (int j = 0; j < 4; j++)
#pragma unroll
            for (int r = 0; r < 4; r++) acc[i][j][r] = 0.f;

    int prow = t >> 1, pq0 = (t & 1) * 2;
#define PREFETCH3(cc) do {                                                      \
        uint32_t st_ = sb + (uint32_t)((cc) % 3) * STAGE3;                      \
        int ko_ = (cc) * 32;                                                    \
        _Pragma("unroll")                                                       \
        for (int i_ = 0; i_ < 2; i_++) {                                        \
            int q_ = pq0 + i_;                                                  \
            uint32_t d_ = st_ + prow * 80 + q_ * 16;                            \
            int go_ = ko_ + q_ * 8;                                             \
            cpa(d_,                gAh + (size_t)prow * CH + go_);              \
            cpa(d_ + PART_BYTES,   gBh + (size_t)prow * CH + go_);              \
            cpa(d_ + 2*PART_BYTES, gBl + (size_t)prow * CH + go_);              \
        }                                                                       \
    } while (0)

    PREFETCH3(0); CP_COMMIT();
    PREFETCH3(1); CP_COMMIT();
#pragma unroll
    for (int c = 0; c < 8; c++) {            // K=256 -> 8 chunks
        if (c < 7) { CP_WAIT1(); } else { CP_WAIT0(); }
        __syncthreads();
        if (c < 6) { PREFETCH3(c + 2); CP_COMMIT(); }
        uint32_t st = sb + (uint32_t)(c % 3) * STAGE3;
#pragma unroll
        for (int s16 = 0; s16 < 2; s16++) {
            uint32_t ah[4][4], bh[2][4], bl[2][4];
            uint32_t aoff = (uint32_t)((wm * 64 + (l & 15)) * 80 + s16 * 32 +
                                       (l >> 4) * 16);
#pragma unroll
            for (int mt = 0; mt < 4; mt++)
                LDSM4(ah[mt], st + aoff + mt * 16 * 80);
            int g = l >> 3;
            uint32_t boff = (uint32_t)((wn * 32 + ((g >> 1) << 3) + (l & 7)) * 80 +
                                       s16 * 32 + (g & 1) * 16);
#pragma unroll
            for (int p = 0; p < 2; p++) {
                LDSM4(bh[p], st + PART_BYTES + boff + p * 16 * 80);
                LDSM4(bl[p], st + 2 * PART_BYTES + boff + p * 16 * 80);
            }
#pragma unroll
            for (int mt = 0; mt < 4; mt++)
#pragma unroll
                for (int nt = 0; nt < 4; nt++) {
                    int p = nt >> 1, h = (nt & 1) * 2;
                    MMA16(acc[mt][nt], ah[mt], bh[p][h], bh[p][h + 1]);
                    MMA16(acc[mt][nt], ah[mt], bl[p][h], bl[p][h + 1]);
                }
        }
    }
#undef PREFETCH3

    // epilogue: tile rowmax -> P=4096*exp(S-max) fp16 -> global (staged)
    __half* pst = (__half*)smraw;                       // [128][136] halves
    float* wmaxs = (float*)(smraw + 36864);             // [128][4]
    float* wsums = wmaxs + 512;
    __syncthreads();
#pragma unroll
    for (int mt = 0; mt < 4; mt++)
#pragma unroll
        for (int hh = 0; hh < 2; hh++) {
            int row = wm * 64 + mt * 16 + hh * 8 + (l >> 2);
            float vmax = -3.0e38f;
#pragma unroll
            for (int nt = 0; nt < 4; nt++)
                vmax = fmaxf(vmax, fmaxf(acc[mt][nt][hh * 2],
                                         acc[mt][nt][hh * 2 + 1]));
#pragma unroll
            for (int off = 1; off <= 2; off <<= 1)
                vmax = fmaxf(vmax, __shfl_xor_sync(0xffffffffu, vmax, off));
            if ((l & 3) == 0) wmaxs[row * 4 + wn] = vmax;
        }
    __syncthreads();
#pragma unroll
    for (int mt = 0; mt < 4; mt++)
#pragma unroll
        for (int hh = 0; hh < 2; hh++) {
            int row = wm * 64 + mt * 16 + hh * 8 + (l >> 2);
            float M = fmaxf(fmaxf(wmaxs[row * 4], wmaxs[row * 4 + 1]),
                            fmaxf(wmaxs[row * 4 + 2], wmaxs[row * 4 + 3]));
            float s = 0.f;
#pragma unroll
            for (int nt = 0; nt < 4; nt++) {
                float e0 = __expf(acc[mt][nt][hh * 2] - M) * PSCALE;
                float e1 = __expf(acc[mt][nt][hh * 2 + 1] - M) * PSCALE;
                s += e0 + e1;
                *(__half2*)&pst[row * 136 + wn * 32 + nt * 8 + 2 * (l & 3)] =
                    __floats2half2_rn(e0, e1);
            }
#pragma unroll
            for (int off = 1; off <= 2; off <<= 1)
                s += __shfl_xor_sync(0xffffffffu, s, off);
            if ((l & 3) == 0) wsums[row * 4 + wn] = s;
        }
    __syncthreads();
    int zb = blockIdx.z;
    if (t < 128) {
        float M = fmaxf(fmaxf(wmaxs[t * 4], wmaxs[t * 4 + 1]),
                        fmaxf(wmaxs[t * 4 + 2], wmaxs[t * 4 + 3]));
        float S = (wsums[t * 4] + wsums[t * 4 + 1] + wsums[t * 4 + 2] +
                   wsums[t * 4 + 3]) * INV_PSCALE;
        g_pmax[(zb * 32 + blockIdx.x) * NPTS + m0 + t] = M;
        g_psum[(zb * 32 + blockIdx.x) * NPTS + m0 + t] = S;
    }
    __half* Pb = g_P + (size_t)zb * NPTS * NPTS;
#pragma unroll
    for (int i = 0; i < 8; i++) {
        int f = t + i * 256;
        int r = f >> 4, c8 = f & 15;
        *(uint4*)(Pb + (size_t)(m0 + r) * NPTS + n0 + c8 * 8) =
            *(const uint4*)&pst[r * 136 + c8 * 8];
    }
}

// ---------------- combine row partials, emit correction factors ------------
__global__ void k_rowstats() {
    int i = blockIdx.x * 256 + threadIdx.x;   // < B*N
    int b = i >> 12, m = i & (NPTS - 1);
    float pm[32];
    float mx = -3.0e38f;
#pragma unroll
    for (int j = 0; j < 32; j++) {
        pm[j] = g_pmax[(b * 32 + j) * NPTS + m];
        mx = fmaxf(mx, pm[j]);
    }
    float s = 0.f;
#pragma unroll
    for (int j = 0; j < 32; j++)
        s += g_psum[(b * 32 + j) * NPTS + m] * __expf(pm[j] - mx);
    float inv = INV_PSCALE / s;
#pragma unroll
    for (int j = 0; j < 32; j++)
        g_f[(b * 32 + j) * NPTS + m] = __expf(pm[j] - mx) * inv;
}

// ---------------- pass 2: column sums = fp16 half2 GEMV ---------------------
__global__ void k_colsum() {      // grid (8, 16, BATCH), 256 threads
    __shared__ float fs[4][256];
    int ng = blockIdx.x, mc = blockIdx.y, b = blockIdx.z, t = threadIdx.x;
#pragma unroll
    for (int jj = 0; jj < 4; jj++)
        fs[jj][t] = g_f[(b * 32 + ng * 4 + jj) * NPTS + mc * 256 + t];
    __syncthreads();
    int n = ng * 512 + 2 * t;
    int jj = t >> 6;
    const __half* P = g_P + (size_t)b * NPTS * NPTS + (size_t)(mc * 256) * NPTS + n;
    float2 a0 = {0, 0}, a1 = {0, 0}, a2 = {0, 0}, a3 = {0, 0};
#pragma unroll 8
    for (int m = 0; m < 256; m += 4) {
        float2 p0 = __half22float2(*(const __half2*)(P + (size_t)(m + 0) * NPTS));
        float2 p1 = __half22float2(*(const __half2*)(P + (size_t)(m + 1) * NPTS));
        float2 p2 = __half22float2(*(const __half2*)(P + (size_t)(m + 2) * NPTS));
        float2 p3 = __half22float2(*(const __half2*)(P + (size_t)(m + 3) * NPTS));
        a0.x = fmaf(p0.x, fs[jj][m + 0], a0.x); a0.y = fmaf(p0.y, fs[jj][m + 0], a0.y);
        a1.x = fmaf(p1.x, fs[jj][m + 1], a1.x); a1.y = fmaf(p1.y, fs[jj][m + 1], a1.y);
        a2.x = fmaf(p2.x, fs[jj][m + 2], a2.x); a2.y = fmaf(p2.y, fs[jj][m + 2], a2.y);
        a3.x = fmaf(p3.x, fs[jj][m + 3], a3.x); a3.y = fmaf(p3.y, fs[jj][m + 3], a3.y);
    }
    float2 r;
    r.x = (a0.x + a1.x) + (a2.x + a3.x);
    r.y = (a0.y + a1.y) + (a2.y + a3.y);
    *(float2*)(&g_colpart[(mc * BATCH + b) * NPTS + n]) = r;
}

// ---------------- gate + gate*V + split -------------------------------------
__global__ void k_gatev() {
    int i4 = blockIdx.x * 256 + threadIdx.x;
    int bn = i4 >> 6;
    float c = 0.f;
#pragma unroll
    for (int y = 0; y < 16; y++) c += g_colpart[y * BATCH * NPTS + bn];
    float gt = c / (ATTN_EPS + c);
    float4 v = ((const float4*)g_V)[i4];
    __half2 h0, l0, h1, l1;
    split2(gt * v.x, gt * v.y, h0, l0);
    split2(gt * v.z, gt * v.w, h1, l1);
    uint2 hv, lv;
    hv.x = *(uint32_t*)&h0; hv.y = *(uint32_t*)&h1;
    lv.x = *(uint32_t*)&l0; lv.y = *(uint32_t*)&l1;
    ((uint2*)g_Th)[i4] = hv;
    ((uint2*)g_Tl)[i4] = lv;
}

// ---------------------------------------------------------------------------
extern "C" void kernel_launch(void* const* d_in, const int* in_sizes, int n_in,
                              void* d_out, int out_size) {
    const float* inp  = (const float*)d_in[0];
    const float* w0   = (const float*)d_in[1];
    const float* b0   = (const float*)d_in[2];
    const float* ln0s = (const float*)d_in[3];
    const float* ln0b = (const float*)d_in[4];
    const float* w1   = (const float*)d_in[5];
    const float* b1   = (const float*)d_in[6];
    const float* ln1s = (const float*)d_in[7];
    const float* ln1b = (const float*)d_in[8];
    const float* wq   = (const float*)d_in[9];
    const float* bq   = (const float*)d_in[10];
    const float* wk   = (const float*)d_in[11];
    const float* bk   = (const float*)d_in[12];
    const float* wv   = (const float*)d_in[13];
    const float* bv   = (const float*)d_in[14];
    const float* wo   = (const float*)d_in[15];
    const float* bo   = (const float*)d_in[16];
    const float* alns = (const float*)d_in[17];
    const float* alnb = (const float*)d_in[18];
    const float* wf   = (const float*)d_in[19];
    const float* bf   = (const float*)d_in[20];

    float *T, *X, *V, *O, *BQKV;
    __half *Xh, *Xl, *Qh, *Kh, *Kl, *Th, *Tl, *CATh, *CATl;
    __half *Wqkvh, *Wqkvl, *Woh, *Wol, *W1h, *W1l, *Wfh, *Wfl;
    cudaGetSymbolAddress((void**)&T, g_T);
    cudaGetSymbolAddress((void**)&X, g_X);
    cudaGetSymbolAddress((void**)&V, g_V);
    cudaGetSymbolAddress((void**)&O, g_O);
    cudaGetSymbolAddress((void**)&BQKV, g_bqkv);
    cudaGetSymbolAddress((void**)&Xh, g_Xh);   cudaGetSymbolAddress((void**)&Xl, g_Xl);
    cudaGetSymbolAddress((void**)&Qh, g_Qh);
    cudaGetSymbolAddress((void**)&Kh, g_Kh);   cudaGetSymbolAddress((void**)&Kl, g_Kl);
    cudaGetSymbolAddress((void**)&Th, g_Th);   cudaGetSymbolAddress((void**)&Tl, g_Tl);
    cudaGetSymbolAddress((void**)&CATh, g_CATh); cudaGetSymbolAddress((void**)&CATl, g_CATl);
    cudaGetSymbolAddress((void**)&Wqkvh, g_Wqkvh); cudaGetSymbolAddress((void**)&Wqkvl, g_Wqkvl);
    cudaGetSymbolAddress((void**)&Woh, g_Woh); cudaGetSymbolAddress((void**)&Wol, g_Wol);
    cudaGetSymbolAddress((void**)&W1h, g_W1h); cudaGetSymbolAddress((void**)&W1l, g_W1l);
    cudaGetSymbolAddress((void**)&Wfh, g_Wfh); cudaGetSymbolAddress((void**)&Wfl, g_Wfl);

    cudaFuncSetAttribute(k_mma<0>, cudaFuncAttributeMaxDynamicSharedMemorySize, MMA_SMEM4);
    cudaFuncSetAttribute(k_mma<3>, cudaFuncAttributeMaxDynamicSharedMemorySize, MMA_SMEM4);
    cudaFuncSetAttribute(k_qk, cudaFuncAttributeMaxDynamicSharedMemorySize, QK_SMEM);

    dim3 lnStats(CH / 64, BATCH, LN_SPLIT);          // (4, 2, 32) = 256 blocks
    const int applyGrid = (int)(MROWS * CH / 4 / 256);
    dim3 gridC(CH / 128, (int)(MROWS / 128));        // (2, 64)
    dim3 gridQKV(768 / 128, (int)(MROWS / 128));     // (6, 64)
    dim3 gridQK(NPTS / 128, NPTS / 128, BATCH);      // (32, 32, 2)
    dim3 gridF(FDIM / 128, (int)(MROWS / 128));      // (8, 64)

    // prep: one merged weight transpose/split + bias pack
    k_prepW<<<8448, 256>>>(wq, wk, wv, wo, w1, wf);
    k_prepB<<<NLAYER * 768 / 256, 256>>>(bq, bk, bv);

    // pre-conv stack
    k_inproj<<<BATCH * NPTS * CH / 256, 256>>>(inp, w0, b0);
    k_ln_stats<<<lnStats, 256>>>(T, ln0s, ln0b);
    k_ln_apply<<<applyGrid, 256>>>(T, nullptr, Xh, Xl, CH, 0, nullptr, 0);
    k_mma<0><<<gridC, 256, MMA_SMEM4>>>(Xh, Xl, CH, W1h, W1l, CH, b1,
                                        O, nullptr, nullptr, CH, CH,
                                        nullptr, nullptr);
    k_ln_stats<<<lnStats, 256>>>(O, ln1s, ln1b);
    k_ln_apply<<<applyGrid, 256>>>(O, X, Xh, Xl, CH, 0, nullptr, 0);

    for (int i = 0; i < NLAYER; i++) {
        const __half* Ahh = (i == 0) ? Xh : CATh + (size_t)(i - 1) * CH;
        const __half* All = (i == 0) ? Xl : CATl + (size_t)(i - 1) * CH;
        int ldA = (i == 0) ? CH : CATDIM;
        // fused QKV
        k_mma<3><<<gridQKV, 256, MMA_SMEM4>>>(
            Ahh, All, ldA, Wqkvh + (size_t)i * 768 * CH,
            Wqkvl + (size_t)i * 768 * CH, CH, BQKV + i * 768,
            V, Qh, nullptr, CH, CH, Kh, Kl);
        k_qk<<<gridQK, 256, QK_SMEM>>>(Qh, Kh, Kl);
        k_rowstats<<<BATCH * NPTS / 256, 256>>>();
        k_colsum<<<dim3(8, 16, BATCH), 256>>>();
        k_gatev<<<(int)(MROWS * CH / 4 / 256), 256>>>();
        k_mma<0><<<gridC, 256, MMA_SMEM4>>>(Th, Tl, CH,
                                            Woh + (size_t)i * CH * CH,
                                            Wol + (size_t)i * CH * CH,
                                            CH, bo + i * CH, O, nullptr, nullptr,
                                            CH, CH, nullptr, nullptr);
        k_ln_stats<<<lnStats, 256>>>(O, alns + i * CH, alnb + i * CH);
        k_ln_apply<<<applyGrid, 256>>>(O, X, CATh, CATl, CATDIM, i * CH, X, 1);
    }

    k_mma<0><<<gridF, 256, MMA_SMEM4>>>(CATh, CATl, CATDIM, Wfh, Wfl, CATDIM, bf,
                                        (float*)d_out, nullptr, nullptr, FDIM,
                                        CATDIM, nullptr, nullptr);
}

// round 16
// speedup vs baseline: 1.1486x; 1.0784x over previous
#include <cuda_runtime.h>
#include <cuda_fp16.h>
#include <math.h>
#include <stdint.h>

#define BATCH 2
#define NPTS 4096
#define CH 256
#define NLAYER 4
#define FDIM 1024
#define CATDIM 1024
#define MROWS ((size_t)BATCH * NPTS)
#define LN_EPS 1e-6f
#define ATTN_EPS 1e-9f
#define LN_SPLIT 32
#define PSCALE 4096.0f
#define INV_PSCALE (1.0f / 4096.0f)

#define PART_BYTES 10240            // 128 rows * 80B (64B data + 16B pad)
#define STAGE4 (4 * PART_BYTES)     // 40960
#define STAGE3 (3 * PART_BYTES)     // 30720
#define MMA_SMEM4 (2 * STAGE4)      // 81920 (2-stage, 2 CTA/SM)
#define QK_SMEM   (3 * STAGE3)      // 92160 (3-stage, 2 CTA/SM)

// ---------------- scratch (device globals) ----------------------------------
__device__ float g_T[BATCH * NPTS * CH];
__device__ float g_X[BATCH * NPTS * CH];
__device__ float g_V[BATCH * NPTS * CH];
__device__ float g_O[BATCH * NPTS * CH];
__device__ __half g_P[(size_t)BATCH * NPTS * NPTS];   // 67MB: 4096*exp(S-tilemax)
__device__ float g_pmax[BATCH * 32 * NPTS];
__device__ float g_psum[BATCH * 32 * NPTS];
__device__ float g_colpart[16 * BATCH * NPTS];
__device__ float g_lnp0[LN_SPLIT * BATCH * CH];
__device__ float g_lnp1[LN_SPLIT * BATCH * CH];
__device__ float g_lncA[BATCH * CH];
__device__ float g_lncB[BATCH * CH];
__device__ unsigned g_lncnt;                 // zero-init, reset by last block
__device__ float g_bqkv[NLAYER * 768];

// half-split operand buffers
__device__ __half g_Xh[MROWS * CH],  g_Xl[MROWS * CH];
__device__ __half g_Qh[MROWS * CH];
__device__ __half g_Kh[MROWS * CH],  g_Kl[MROWS * CH];
__device__ __half g_Th[MROWS * CH],  g_Tl[MROWS * CH];
__device__ __half g_CATh[MROWS * CATDIM], g_CATl[MROWS * CATDIM];
__device__ __half g_Wqkvh[NLAYER * 768 * CH], g_Wqkvl[NLAYER * 768 * CH];
__device__ __half g_Woh[NLAYER * CH * CH], g_Wol[NLAYER * CH * CH];
__device__ __half g_W1h[CH * CH], g_W1l[CH * CH];
__device__ __half g_Wfh[CATDIM * FDIM], g_Wfl[CATDIM * FDIM];

// ---------------- PTX helpers ------------------------------------------------
__device__ __forceinline__ uint32_t smem_u32(const void* p) {
    uint32_t a;
    asm("{ .reg .u64 t; cvta.to.shared.u64 t, %1; cvt.u32.u64 %0, t; }"
        : "=r"(a) : "l"(p));
    return a;
}
__device__ __forceinline__ void cpa(uint32_t dst, const void* src) {
    asm volatile("cp.async.cg.shared.global [%0], [%1], 16;"
                 :: "r"(dst), "l"(src));
}
#define CP_COMMIT() asm volatile("cp.async.commit_group;" ::: "memory")
#define CP_WAIT1() asm volatile("cp.async.wait_group 1;" ::: "memory")
#define CP_WAIT0() asm volatile("cp.async.wait_group 0;" ::: "memory")

#define LDSM4(r, addr)                                                          \
    asm volatile("ldmatrix.sync.aligned.m8n8.x4.shared.b16 {%0,%1,%2,%3}, [%4];"\
        : "=r"((r)[0]), "=r"((r)[1]), "=r"((r)[2]), "=r"((r)[3]) : "r"(addr))

#define MMA16(d, a, b0r, b1r)                                                   \
    asm volatile("mma.sync.aligned.m16n8k16.row.col.f32.f16.f16.f32 "           \
        "{%0,%1,%2,%3}, {%4,%5,%6,%7}, {%8,%9}, {%0,%1,%2,%3};"                 \
        : "+f"((d)[0]), "+f"((d)[1]), "+f"((d)[2]), "+f"((d)[3])                \
        : "r"((a)[0]), "r"((a)[1]), "r"((a)[2]), "r"((a)[3]), "r"(b0r), "r"(b1r))

__device__ __forceinline__ void split2(float v0, float v1, __half2& hi, __half2& lo) {
    __half h0 = __float2half_rn(v0), h1 = __float2half_rn(v1);
    hi = __halves2half2(h0, h1);
    lo = __halves2half2(__float2half_rn(v0 - __half2float(h0)),
                        __float2half_rn(v1 - __half2float(h1)));
}

// ---------------- merged weight prep: transpose + fp16 hi/lo split ----------
__global__ void k_prepW(const float* __restrict__ wq, const float* __restrict__ wk,
                        const float* __restrict__ wv, const float* __restrict__ wo,
                        const float* __restrict__ w1, const float* __restrict__ wf) {
    int e = blockIdx.x * 256 + threadIdx.x;
    float x;
    size_t o;
    __half *dh, *dl;
    if (e < 1048576) {
        int seg = e >> 18;
        int r = e & 262143;
        int lz = r >> 16;
        int ee = r & 65535;
        int k = ee >> 8, n = ee & 255;
        const float* W = (seg == 0) ? wq : (seg == 1) ? wk : (seg == 2) ? wv : wo;
        x = W[(size_t)lz * 65536 + ee];
        if (seg < 3) {
            o = (size_t)lz * 768 * CH + (size_t)seg * 256 * CH + (size_t)n * CH + k;
            dh = g_Wqkvh; dl = g_Wqkvl;
        } else {
            o = (size_t)lz * 65536 + (size_t)n * CH + k;
            dh = g_Woh; dl = g_Wol;
        }
    } else if (e < 1114112) {
        int ee = e - 1048576;
        int k = ee >> 8, n = ee & 255;
        x = w1[ee];
        o = (size_t)n * CH + k;
        dh = g_W1h; dl = g_W1l;
    } else {
        int ee = e - 1114112;
        int k = ee >> 10, n = ee & 1023;
        x = wf[ee];
        o = (size_t)n * CATDIM + k;
        dh = g_Wfh; dl = g_Wfl;
    }
    __half h = __float2half_rn(x);
    dh[o] = h;
    dl[o] = __float2half_rn(x - __half2float(h));
}

__global__ void k_prepB(const float* __restrict__ bq, const float* __restrict__ bk,
                        const float* __restrict__ bv) {
    int i = blockIdx.x * 256 + threadIdx.x;      // < NLAYER*768
    int lz = i / 768, r = i - lz * 768;
    float v = (r < 256) ? bq[lz * CH + r]
            : (r < 512) ? bk[lz * CH + r - 256]
                        : bv[lz * CH + r - 512];
    g_bqkv[i] = v;
}

// ---------------- input projection ------------------------------------------
__global__ void k_inproj(const float* __restrict__ in, const float* __restrict__ w0,
                         const float* __restrict__ b0) {
    int idx = blockIdx.x * 256 + threadIdx.x;
    int c = idx & (CH - 1);
    int bn = idx >> 8;
    const float* xp = in + bn * 3;
    float acc = b0[c];
    acc = fmaf(xp[0], w0[c], acc);
    acc = fmaf(xp[1], w0[CH + c], acc);
    acc = fmaf(xp[2], w0[2 * CH + c], acc);
    g_T[idx] = acc;
}

// ---------------- LayerNorm stats (512 thr) + fused coef (last block) -------
// grid (CH/64, BATCH, LN_SPLIT) = (4, 2, 32) = 256 blocks, 512 threads
__global__ void k_ln_stats(const float* __restrict__ src,
                           const float* __restrict__ scale,
                           const float* __restrict__ bias) {
    int t = threadIdx.x;
    int c4i = t & 15, nr = t >> 4;        // 16 float4 columns x 32 row groups
    int c0 = blockIdx.x * 64 + c4i * 4;
    int b = blockIdx.y, sp = blockIdx.z;
    const float4* p = (const float4*)(src +
        ((size_t)b * NPTS + sp * (NPTS / LN_SPLIT)) * CH + c0);
    float4 s0 = {0, 0, 0, 0}, s1 = {0, 0, 0, 0};
#pragma unroll
    for (int n = nr; n < NPTS / LN_SPLIT; n += 32) {
        float4 v = p[(size_t)n * (CH / 4)];
        s0.x += v.x; s1.x = fmaf(v.x, v.x, s1.x);
        s0.y += v.y; s1.y = fmaf(v.y, v.y, s1.y);
        s0.z += v.z; s1.z = fmaf(v.z, v.z, s1.z);
        s0.w += v.w; s1.w = fmaf(v.w, v.w, s1.w);
    }
    __shared__ float sh0[32][68], sh1[32][68];
    sh0[nr][c4i * 4 + 0] = s0.x; sh1[nr][c4i * 4 + 0] = s1.x;
    sh0[nr][c4i * 4 + 1] = s0.y; sh1[nr][c4i * 4 + 1] = s1.y;
    sh0[nr][c4i * 4 + 2] = s0.z; sh1[nr][c4i * 4 + 2] = s1.z;
    sh0[nr][c4i * 4 + 3] = s0.w; sh1[nr][c4i * 4 + 3] = s1.w;
    __syncthreads();
    if (t < 64) {
        float a0 = 0.f, a1 = 0.f;
#pragma unroll
        for (int r = 0; r < 32; r++) { a0 += sh0[r][t]; a1 += sh1[r][t]; }
        g_lnp0[(sp * BATCH + b) * CH + blockIdx.x * 64 + t] = a0;
        g_lnp1[(sp * BATCH + b) * CH + blockIdx.x * 64 + t] = a1;
    }
    // last of 256 blocks computes the coefficients (one (b,c) per thread)
    __threadfence();
    __shared__ bool lastb;
    if (t == 0) lastb = (atomicAdd(&g_lncnt, 1u) == 255u);
    __syncthreads();
    if (lastb) {
        int e = t;                          // BATCH*CH == 512 == blockDim
        int cc = e & (CH - 1);
        float s0c = 0.f, s1c = 0.f;
#pragma unroll
        for (int j = 0; j < LN_SPLIT; j++) {
            s0c += g_lnp0[j * BATCH * CH + e];
            s1c += g_lnp1[j * BATCH * CH + e];
        }
        float mu = s0c * (1.0f / NPTS), m2 = s1c * (1.0f / NPTS);
        float rstd = rsqrtf(m2 - mu * mu + LN_EPS);
        float a = scale[cc] * rstd;
        g_lncA[e] = a;
        g_lncB[e] = bias[cc] - mu * a;
        if (t == 0) g_lncnt = 0u;
    }
}

__global__ void k_ln_apply(const float* __restrict__ src, float* __restrict__ dstF,
                           __half* __restrict__ dH, __half* __restrict__ dL,
                           int ldH, int coff, const float* __restrict__ resid,
                           int relu_mode) {
    int i4 = blockIdx.x * 256 + threadIdx.x;
    int c4 = i4 & 63;
    int bn = i4 >> 6;
    int b = bn >> 12;
    float4 x = ((const float4*)src)[i4];
    float4 a = ((const float4*)g_lncA)[b * 64 + c4];
    float4 bb = ((const float4*)g_lncB)[b * 64 + c4];
    float4 y;
    y.x = fmaf(x.x, a.x, bb.x); y.y = fmaf(x.y, a.y, bb.y);
    y.z = fmaf(x.z, a.z, bb.z); y.w = fmaf(x.w, a.w, bb.w);
    if (relu_mode) {
        float4 r = ((const float4*)resid)[i4];
        y.x = fmaxf(y.x, 0.f) + r.x; y.y = fmaxf(y.y, 0.f) + r.y;
        y.z = fmaxf(y.z, 0.f) + r.z; y.w = fmaxf(y.w, 0.f) + r.w;
    }
    if (dstF) ((float4*)dstF)[i4] = y;
    __half2 h0, l0, h1, l1;
    split2(y.x, y.y, h0, l0);
    split2(y.z, y.w, h1, l1);
    size_t hidx = (size_t)bn * (ldH >> 2) + (coff >> 2) + c4;
    uint2 hv, lv;
    hv.x = *(uint32_t*)&h0; hv.y = *(uint32_t*)&h1;
    lv.x = *(uint32_t*)&l0; lv.y = *(uint32_t*)&l1;
    ((uint2*)dH)[hidx] = hv;
    ((uint2*)dL)[hidx] = lv;
}

// ---------------- fp16x3 tensor GEMM (2-stage, 2 CTA/SM): C = A * B^T -------
// MODE 0: Cf = acc + bias (fp32). MODE 3: fused QKV epilogue routing
// (bx 0-1 -> Q hi only; 2-3 -> K hi/lo split; 4-5 -> V fp32).
template <int MODE>
__global__ void __launch_bounds__(256, 2) k_mma(
    const __half* __restrict__ Ah, const __half* __restrict__ Al, int ldA,
    const __half* __restrict__ Bh, const __half* __restrict__ Bl, int ldB,
    const float* __restrict__ bias,
    float* __restrict__ Cf, __half* __restrict__ Chi, __half* __restrict__ Clo,
    int ldC, int K, __half* __restrict__ Chi2, __half* __restrict__ Clo2) {
    extern __shared__ char smraw[];
    uint32_t sb = smem_u32(smraw);
    int t = threadIdx.x, l = t & 31, wid = t >> 5;
    int wm = wid >> 2, wn = wid & 3;
    int m0 = blockIdx.y * 128, n0 = blockIdx.x * 128;
    const __half* gAh = Ah + (size_t)m0 * ldA;
    const __half* gAl = Al + (size_t)m0 * ldA;
    const __half* gBh = Bh + (size_t)n0 * ldB;
    const __half* gBl = Bl + (size_t)n0 * ldB;

    float acc[4][4][4];
#pragma unroll
    for (int i = 0; i < 4; i++)
#pragma unroll
        for (int j = 0; j < 4; j++)
#pragma unroll
            for (int r = 0; r < 4; r++) acc[i][j][r] = 0.f;

    int prow = t >> 1, pq0 = (t & 1) * 2;
#define PREFETCH4(cc) do {                                                      \
        uint32_t st_ = sb + (uint32_t)((cc) & 1) * STAGE4;                      \
        int ko_ = (cc) * 32;                                                    \
        _Pragma("unroll")                                                       \
        for (int i_ = 0; i_ < 2; i_++) {                                        \
            int q_ = pq0 + i_;                                                  \
            uint32_t d_ = st_ + prow * 80 + q_ * 16;                            \
            int go_ = ko_ + q_ * 8;                                             \
            cpa(d_,                gAh + (size_t)prow * ldA + go_);             \
            cpa(d_ + PART_BYTES,   gAl + (size_t)prow * ldA + go_);             \
            cpa(d_ + 2*PART_BYTES, gBh + (size_t)prow * ldB + go_);             \
            cpa(d_ + 3*PART_BYTES, gBl + (size_t)prow * ldB + go_);             \
        }                                                                       \
    } while (0)

    int NC = K >> 5;
    PREFETCH4(0);
    CP_COMMIT();
    for (int c = 0; c < NC; c++) {
        if (c + 1 < NC) {
            PREFETCH4(c + 1);
            CP_COMMIT();
            CP_WAIT1();
        } else {
            CP_WAIT0();
        }
        __syncthreads();
        uint32_t st = sb + (uint32_t)(c & 1) * STAGE4;
#pragma unroll
        for (int s16 = 0; s16 < 2; s16++) {
            uint32_t ah[4][4], al[4][4], bh[2][4], bl[2][4];
            uint32_t aoff = (uint32_t)((wm * 64 + (l & 15)) * 80 + s16 * 32 +
                                       (l >> 4) * 16);
#pragma unroll
            for (int mt = 0; mt < 4; mt++) {
                LDSM4(ah[mt], st + aoff + mt * 16 * 80);
                LDSM4(al[mt], st + PART_BYTES + aoff + mt * 16 * 80);
            }
            int g = l >> 3;
            uint32_t boff = (uint32_t)((wn * 32 + ((g >> 1) << 3) + (l & 7)) * 80 +
                                       s16 * 32 + (g & 1) * 16);
#pragma unroll
            for (int p = 0; p < 2; p++) {
                LDSM4(bh[p], st + 2 * PART_BYTES + boff + p * 16 * 80);
                LDSM4(bl[p], st + 3 * PART_BYTES + boff + p * 16 * 80);
            }
#pragma unroll
            for (int mt = 0; mt < 4; mt++)
#pragma unroll
                for (int nt = 0; nt < 4; nt++) {
                    int p = nt >> 1, h = (nt & 1) * 2;
                    MMA16(acc[mt][nt], ah[mt], bh[p][h], bh[p][h + 1]);
                    MMA16(acc[mt][nt], ah[mt], bl[p][h], bl[p][h + 1]);
                    MMA16(acc[mt][nt], al[mt], bh[p][h], bh[p][h + 1]);
                }
        }
        __syncthreads();
    }
#undef PREFETCH4

    if (MODE == 0) {
#pragma unroll
        for (int mt = 0; mt < 4; mt++)
#pragma unroll
            for (int hh = 0; hh < 2; hh++) {
                int row = m0 + wm * 64 + mt * 16 + (l >> 2) + hh * 8;
#pragma unroll
                for (int nt = 0; nt < 4; nt++) {
                    int n = n0 + wn * 32 + nt * 8 + 2 * (l & 3);
                    float v0 = acc[mt][nt][hh * 2] + bias[n];
                    float v1 = acc[mt][nt][hh * 2 + 1] + bias[n + 1];
                    *(float2*)(Cf + (size_t)row * ldC + n) = make_float2(v0, v1);
                }
            }
    } else {
        int bx = blockIdx.x;
        __half *dH = nullptr, *dL = nullptr;
        float* dF = nullptr;
        int nb;
        if (bx < 2)      { dH = Chi;  dL = nullptr; nb = 0;   }   // Q: hi only
        else if (bx < 4) { dH = Chi2; dL = Clo2;    nb = 256; }   // K: hi+lo
        else             { dF = Cf;                 nb = 512; }   // V: fp32
#pragma unroll
        for (int mt = 0; mt < 4; mt++)
#pragma unroll
            for (int hh = 0; hh < 2; hh++) {
                int row = m0 + wm * 64 + mt * 16 + (l >> 2) + hh * 8;
#pragma unroll
                for (int nt = 0; nt < 4; nt++) {
                    int n = n0 + wn * 32 + nt * 8 + 2 * (l & 3);
                    float v0 = acc[mt][nt][hh * 2] + bias[n];
                    float v1 = acc[mt][nt][hh * 2 + 1] + bias[n + 1];
                    int col = n - nb;
                    if (dF) {
                        *(float2*)(dF + (size_t)row * CH + col) = make_float2(v0, v1);
                    } else if (dL) {
                        __half2 hv, lv;
                        split2(v0, v1, hv, lv);
                        *(__half2*)(dH + (size_t)row * CH + col) = hv;
                        *(__half2*)(dL + (size_t)row * CH + col) = lv;
                    } else {
                        *(__half2*)(dH + (size_t)row * CH + col) =
                            __floats2half2_rn(v0, v1);
                    }
                }
            }
    }
}

// ---------------- QK kernel: 2-pass fp16, 3-stage, 2 CTA/SM -----------------
__global__ void __launch_bounds__(256, 2) k_qk(const __half* __restrict__ Ah,
                                               const __half* __restrict__ Bh,
                                               const __half* __restrict__ Bl) {
    extern __shared__ char smraw[];
    uint32_t sb = smem_u32(smraw);
    int t = threadIdx.x, l = t & 31, wid = t >> 5;
    int wm = wid >> 2, wn = wid & 3;
    int m0 = blockIdx.y * 128, n0 = blockIdx.x * 128;
    size_t z = (size_t)blockIdx.z * NPTS * CH;
    const __half* gAh = Ah + z + (size_t)m0 * CH;
    const __half* gBh = Bh + z + (size_t)n0 * CH;
    const __half* gBl = Bl + z + (size_t)n0 * CH;

    float acc[4][4][4];
#pragma unroll
    for (int i = 0; i < 4; i++)
#pragma unroll
        for (int j = 0; j < 4; j++)
#pragma unroll
            for (int r = 0; r < 4; r++) acc[i][j][r] = 0.f;

    int prow = t >> 1, pq0 = (t & 1) * 2;
#define PREFETCH3(cc) do {                                                      \
        uint32_t st_ = sb + (uint32_t)((cc) % 3) * STAGE3;                      \
        int ko_ = (cc) * 32;                                                    \
        _Pragma("unroll")                                                       \
        for (int i_ = 0; i_ < 2; i_++) {                                        \
            int q_ = pq0 + i_;                                                  \
            uint32_t d_ = st_ + prow * 80 + q_ * 16;                            \
            int go_ = ko_ + q_ * 8;                                             \
            cpa(d_,                gAh + (size_t)prow * CH + go_);              \
            cpa(d_ + PART_BYTES,   gBh + (size_t)prow * CH + go_);              \
            cpa(d_ + 2*PART_BYTES, gBl + (size_t)prow * CH + go_);              \
        }                                                                       \
    } while (0)

    PREFETCH3(0); CP_COMMIT();
    PREFETCH3(1); CP_COMMIT();
#pragma unroll
    for (int c = 0; c < 8; c++) {            // K=256 -> 8 chunks
        if (c < 7) { CP_WAIT1(); } else { CP_WAIT0(); }
        __syncthreads();
        if (c < 6) { PREFETCH3(c + 2); CP_COMMIT(); }
        uint32_t st = sb + (uint32_t)(c % 3) * STAGE3;
#pragma unroll
        for (int s16 = 0; s16 < 2; s16++) {
            uint32_t ah[4][4], bh[2][4], bl[2][4];
            uint32_t aoff = (uint32_t)((wm * 64 + (l & 15)) * 80 + s16 * 32 +
                                       (l >> 4) * 16);
#pragma unroll
            for (int mt = 0; mt < 4; mt++)
                LDSM4(ah[mt], st + aoff + mt * 16 * 80);
            int g = l >> 3;
            uint32_t boff = (uint32_t)((wn * 32 + ((g >> 1) << 3) + (l & 7)) * 80 +
                                       s16 * 32 + (g & 1) * 16);
#pragma unroll
            for (int p = 0; p < 2; p++) {
                LDSM4(bh[p], st + PART_BYTES + boff + p * 16 * 80);
                LDSM4(bl[p], st + 2 * PART_BYTES + boff + p * 16 * 80);
            }
#pragma unroll
            for (int mt = 0; mt < 4; mt++)
#pragma unroll
                for (int nt = 0; nt < 4; nt++) {
                    int p = nt >> 1, h = (nt & 1) * 2;
                    MMA16(acc[mt][nt], ah[mt], bh[p][h], bh[p][h + 1]);
                    MMA16(acc[mt][nt], ah[mt], bl[p][h], bl[p][h + 1]);
                }
        }
    }
#undef PREFETCH3

    // epilogue: tile rowmax -> P=4096*exp(S-max) fp16 -> global (staged)
    __half* pst = (__half*)smraw;                       // [128][136] halves
    float* wmaxs = (float*)(smraw + 36864);             // [128][4]
    float* wsums = wmaxs + 512;
    __syncthreads();
#pragma unroll
    for (int mt = 0; mt < 4; mt++)
#pragma unroll
        for (int hh = 0; hh < 2; hh++) {
            int row = wm * 64 + mt * 16 + hh * 8 + (l >> 2);
            float vmax = -3.0e38f;
#pragma unroll
            for (int nt = 0; nt < 4; nt++)
                vmax = fmaxf(vmax, fmaxf(acc[mt][nt][hh * 2],
                                         acc[mt][nt][hh * 2 + 1]));
#pragma unroll
            for (int off = 1; off <= 2; off <<= 1)
                vmax = fmaxf(vmax, __shfl_xor_sync(0xffffffffu, vmax, off));
            if ((l & 3) == 0) wmaxs[row * 4 + wn] = vmax;
        }
    __syncthreads();
#pragma unroll
    for (int mt = 0; mt < 4; mt++)
#pragma unroll
        for (int hh = 0; hh < 2; hh++) {
            int row = wm * 64 + mt * 16 + hh * 8 + (l >> 2);
            float M = fmaxf(fmaxf(wmaxs[row * 4], wmaxs[row * 4 + 1]),
                            fmaxf(wmaxs[row * 4 + 2], wmaxs[row * 4 + 3]));
            float s = 0.f;
#pragma unroll
            for (int nt = 0; nt < 4; nt++) {
                float e0 = __expf(acc[mt][nt][hh * 2] - M) * PSCALE;
                float e1 = __expf(acc[mt][nt][hh * 2 + 1] - M) * PSCALE;
                s += e0 + e1;
                *(__half2*)&pst[row * 136 + wn * 32 + nt * 8 + 2 * (l & 3)] =
                    __floats2half2_rn(e0, e1);
            }
#pragma unroll
            for (int off = 1; off <= 2; off <<= 1)
                s += __shfl_xor_sync(0xffffffffu, s, off);
            if ((l & 3) == 0) wsums[row * 4 + wn] = s;
        }
    __syncthreads();
    int zb = blockIdx.z;
    if (t < 128) {
        float M = fmaxf(fmaxf(wmaxs[t * 4], wmaxs[t * 4 + 1]),
                        fmaxf(wmaxs[t * 4 + 2], wmaxs[t * 4 + 3]));
        float S = (wsums[t * 4] + wsums[t * 4 + 1] + wsums[t * 4 + 2] +
                   wsums[t * 4 + 3]) * INV_PSCALE;
        g_pmax[(zb * 32 + blockIdx.x) * NPTS + m0 + t] = M;
        g_psum[(zb * 32 + blockIdx.x) * NPTS + m0 + t] = S;
    }
    __half* Pb = g_P + (size_t)zb * NPTS * NPTS;
#pragma unroll
    for (int i = 0; i < 8; i++) {
        int f = t + i * 256;
        int r = f >> 4, c8 = f & 15;
        *(uint4*)(Pb + (size_t)(m0 + r) * NPTS + n0 + c8 * 8) =
            *(const uint4*)&pst[r * 136 + c8 * 8];
    }
}

// ---------------- pass 2: fused rowstats + column sums ----------------------
__global__ void k_colsum() {      // grid (8, 16, BATCH), 256 threads
    __shared__ float fs[4][256];
    int ng = blockIdx.x, mc = blockIdx.y, b = blockIdx.z, t = threadIdx.x;
    // row stats for m = mc*256 + t (redundant across ng; L2-resident)
    {
        int m = mc * 256 + t;
        float pm[32];
        float mx = -3.0e38f;
#pragma unroll
        for (int j = 0; j < 32; j++) {
            pm[j] = g_pmax[(b * 32 + j) * NPTS + m];
            mx = fmaxf(mx, pm[j]);
        }
        float s = 0.f;
#pragma unroll
        for (int j = 0; j < 32; j++)
            s += g_psum[(b * 32 + j) * NPTS + m] * __expf(pm[j] - mx);
        float inv = INV_PSCALE / s;
#pragma unroll
        for (int jj2 = 0; jj2 < 4; jj2++)
            fs[jj2][t] = __expf(pm[ng * 4 + jj2] - mx) * inv;
    }
    __syncthreads();
    int n = ng * 512 + 2 * t;
    int jj = t >> 6;
    const __half* P = g_P + (size_t)b * NPTS * NPTS + (size_t)(mc * 256) * NPTS + n;
    float2 a0 = {0, 0}, a1 = {0, 0}, a2 = {0, 0}, a3 = {0, 0};
#pragma unroll 8
    for (int m = 0; m < 256; m += 4) {
        float2 p0 = __half22float2(*(const __half2*)(P + (size_t)(m + 0) * NPTS));
        float2 p1 = __half22float2(*(const __half2*)(P + (size_t)(m + 1) * NPTS));
        float2 p2 = __half22float2(*(const __half2*)(P + (size_t)(m + 2) * NPTS));
        float2 p3 = __half22float2(*(const __half2*)(P + (size_t)(m + 3) * NPTS));
        a0.x = fmaf(p0.x, fs[jj][m + 0], a0.x); a0.y = fmaf(p0.y, fs[jj][m + 0], a0.y);
        a1.x = fmaf(p1.x, fs[jj][m + 1], a1.x); a1.y = fmaf(p1.y, fs[jj][m + 1], a1.y);
        a2.x = fmaf(p2.x, fs[jj][m + 2], a2.x); a2.y = fmaf(p2.y, fs[jj][m + 2], a2.y);
        a3.x = fmaf(p3.x, fs[jj][m + 3], a3.x); a3.y = fmaf(p3.y, fs[jj][m + 3], a3.y);
    }
    float2 r;
    r.x = (a0.x + a1.x) + (a2.x + a3.x);
    r.y = (a0.y + a1.y) + (a2.y + a3.y);
    *(float2*)(&g_colpart[(mc * BATCH + b) * NPTS + n]) = r;
}

// ---------------- gate + gate*V + split -------------------------------------
__global__ void k_gatev() {
    int i4 = blockIdx.x * 256 + threadIdx.x;
    int bn = i4 >> 6;
    float c = 0.f;
#pragma unroll
    for (int y = 0; y < 16; y++) c += g_colpart[y * BATCH * NPTS + bn];
    float gt = c / (ATTN_EPS + c);
    float4 v = ((const float4*)g_V)[i4];
    __half2 h0, l0, h1, l1;
    split2(gt * v.x, gt * v.y, h0, l0);
    split2(gt * v.z, gt * v.w, h1, l1);
    uint2 hv, lv;
    hv.x = *(uint32_t*)&h0; hv.y = *(uint32_t*)&h1;
    lv.x = *(uint32_t*)&l0; lv.y = *(uint32_t*)&l1;
    ((uint2*)g_Th)[i4] = hv;
    ((uint2*)g_Tl)[i4] = lv;
}

// ---------------------------------------------------------------------------
extern "C" void kernel_launch(void* const* d_in, const int* in_sizes, int n_in,
                              void* d_out, int out_size) {
    const float* inp  = (const float*)d_in[0];
    const float* w0   = (const float*)d_in[1];
    const float* b0   = (const float*)d_in[2];
    const float* ln0s = (const float*)d_in[3];
    const float* ln0b = (const float*)d_in[4];
    const float* w1   = (const float*)d_in[5];
    const float* b1   = (const float*)d_in[6];
    const float* ln1s = (const float*)d_in[7];
    const float* ln1b = (const float*)d_in[8];
    const float* wq   = (const float*)d_in[9];
    const float* bq   = (const float*)d_in[10];
    const float* wk   = (const float*)d_in[11];
    const float* bk   = (const float*)d_in[12];
    const float* wv   = (const float*)d_in[13];
    const float* bv   = (const float*)d_in[14];
    const float* wo   = (const float*)d_in[15];
    const float* bo   = (const float*)d_in[16];
    const float* alns = (const float*)d_in[17];
    const float* alnb = (const float*)d_in[18];
    const float* wf   = (const float*)d_in[19];
    const float* bf   = (const float*)d_in[20];

    float *T, *X, *V, *O, *BQKV;
    __half *Xh, *Xl, *Qh, *Kh, *Kl, *Th, *Tl, *CATh, *CATl;
    __half *Wqkvh, *Wqkvl, *Woh, *Wol, *W1h, *W1l, *Wfh, *Wfl;
    cudaGetSymbolAddress((void**)&T, g_T);
    cudaGetSymbolAddress((void**)&X, g_X);
    cudaGetSymbolAddress((void**)&V, g_V);
    cudaGetSymbolAddress((void**)&O, g_O);
    cudaGetSymbolAddress((void**)&BQKV, g_bqkv);
    cudaGetSymbolAddress((void**)&Xh, g_Xh);   cudaGetSymbolAddress((void**)&Xl, g_Xl);
    cudaGetSymbolAddress((void**)&Qh, g_Qh);
    cudaGetSymbolAddress((void**)&Kh, g_Kh);   cudaGetSymbolAddress((void**)&Kl, g_Kl);
    cudaGetSymbolAddress((void**)&Th, g_Th);   cudaGetSymbolAddress((void**)&Tl, g_Tl);
    cudaGetSymbolAddress((void**)&CATh, g_CATh); cudaGetSymbolAddress((void**)&CATl, g_CATl);
    cudaGetSymbolAddress((void**)&Wqkvh, g_Wqkvh); cudaGetSymbolAddress((void**)&Wqkvl, g_Wqkvl);
    cudaGetSymbolAddress((void**)&Woh, g_Woh); cudaGetSymbolAddress((void**)&Wol, g_Wol);
    cudaGetSymbolAddress((void**)&W1h, g_W1h); cudaGetSymbolAddress((void**)&W1l, g_W1l);
    cudaGetSymbolAddress((void**)&Wfh, g_Wfh); cudaGetSymbolAddress((void**)&Wfl, g_Wfl);

    cudaFuncSetAttribute(k_mma<0>, cudaFuncAttributeMaxDynamicSharedMemorySize, MMA_SMEM4);
    cudaFuncSetAttribute(k_mma<3>, cudaFuncAttributeMaxDynamicSharedMemorySize, MMA_SMEM4);
    cudaFuncSetAttribute(k_qk, cudaFuncAttributeMaxDynamicSharedMemorySize, QK_SMEM);

    dim3 lnStats(CH / 64, BATCH, LN_SPLIT);          // (4, 2, 32) = 256 blocks
    const int applyGrid = (int)(MROWS * CH / 4 / 256);
    dim3 gridC(CH / 128, (int)(MROWS / 128));        // (2, 64)
    dim3 gridQKV(768 / 128, (int)(MROWS / 128));     // (6, 64)
    dim3 gridQK(NPTS / 128, NPTS / 128, BATCH);      // (32, 32, 2)
    dim3 gridF(FDIM / 128, (int)(MROWS / 128));      // (8, 64)

    // prep: one merged weight transpose/split + bias pack
    k_prepW<<<8448, 256>>>(wq, wk, wv, wo, w1, wf);
    k_prepB<<<NLAYER * 768 / 256, 256>>>(bq, bk, bv);

    // pre-conv stack
    k_inproj<<<BATCH * NPTS * CH / 256, 256>>>(inp, w0, b0);
    k_ln_stats<<<lnStats, 512>>>(T, ln0s, ln0b);
    k_ln_apply<<<applyGrid, 256>>>(T, nullptr, Xh, Xl, CH, 0, nullptr, 0);
    k_mma<0><<<gridC, 256, MMA_SMEM4>>>(Xh, Xl, CH, W1h, W1l, CH, b1,
                                        O, nullptr, nullptr, CH, CH,
                                        nullptr, nullptr);
    k_ln_stats<<<lnStats, 512>>>(O, ln1s, ln1b);
    k_ln_apply<<<applyGrid, 256>>>(O, X, Xh, Xl, CH, 0, nullptr, 0);

    for (int i = 0; i < NLAYER; i++) {
        const __half* Ahh = (i == 0) ? Xh : CATh + (size_t)(i - 1) * CH;
        const __half* All = (i == 0) ? Xl : CATl + (size_t)(i - 1) * CH;
        int ldA = (i == 0) ? CH : CATDIM;
        // fused QKV
        k_mma<3><<<gridQKV, 256, MMA_SMEM4>>>(
            Ahh, All, ldA, Wqkvh + (size_t)i * 768 * CH,
            Wqkvl + (size_t)i * 768 * CH, CH, BQKV + i * 768,
            V, Qh, nullptr, CH, CH, Kh, Kl);
        k_qk<<<gridQK, 256, QK_SMEM>>>(Qh, Kh, Kl);
        k_colsum<<<dim3(8, 16, BATCH), 256>>>();
        k_gatev<<<(int)(MROWS * CH / 4 / 256), 256>>>();
        k_mma<0><<<gridC, 256, MMA_SMEM4>>>(Th, Tl, CH,
                                            Woh + (size_t)i * CH * CH,
                                            Wol + (size_t)i * CH * CH,
                                            CH, bo + i * CH, O, nullptr, nullptr,
                                            CH, CH, nullptr, nullptr);
        k_ln_stats<<<lnStats, 512>>>(O, alns + i * CH, alnb + i * CH);
        k_ln_apply<<<applyGrid, 256>>>(O, X, CATh, CATl, CATDIM, i * CH, X, 1);
    }

    k_mma<0><<<gridF, 256, MMA_SMEM4>>>(CATh, CATl, CATDIM, Wfh, Wfl, CATDIM, bf,
                                        (float*)d_out, nullptr, nullptr, FDIM,
                                        CATDIM, nullptr, nullptr);
}